// round 6
// baseline (speedup 1.0000x reference)
#include <cuda_runtime.h>
#include <cuda_bf16.h>
#include <cstdint>

// ---------------------------------------------------------------------------
// RelGAT restructured:
//   score_e = <h[dst], hW1[src]> + <g[dst], efeat_e>,  g = h@W1^T, hW1 = h@W1+b1
//   neigh_d = ( sum w_e hW1[src] + (sum w_e efeat_e)@W1 ) / denom
// GEMMs: mma.sync m16n8k16 bf16 (bf16x3 fp32 emulation: hh + hl + lh).
// This round: 4 A-sharing GEMMs fused into one launch; K-chunked smem for
// 2 CTAs/SM; ldmatrix x4 for B; sW1 GEMM fused with the finalize epilogue.
// ---------------------------------------------------------------------------

namespace {
constexpr int    NN  = 50000;
constexpr int    NE  = 600000;
constexpr size_t ND  = (size_t)NN * 128;
constexpr float  NEG_SLOPE = 0.22916666666666666f;

constexpr size_t O_HW1  = 0;
constexpr size_t O_G    = 1 * ND;
constexpr size_t O_SELF = 2 * ND;
constexpr size_t O_ISO  = 3 * ND;
constexpr size_t O_WSUM = 4 * ND;
constexpr size_t O_S    = 5 * ND;
constexpr size_t O_H1   = 6 * ND;
constexpr size_t O_SCORE = 7 * ND;
constexpr size_t O_SMAX  = O_SCORE + NE;
constexpr size_t O_DEN   = O_SMAX + NN;
constexpr size_t O_DEG   = O_DEN + NN;
constexpr size_t SCRATCH = O_DEG + NN;

// GEMM smem (bytes). K-chunked tiles (chunk K=64).
// A tile: 128 rows x (64+8) bf16 = 144 B/row  (row stride 36 words = +4 banks)
// B trans tile ([k][n]): 64 rows x (128+8) bf16 = 272 B/row
// B non-trans tile ([n][k]): 128 rows x (64+8) bf16 = 144 B/row
constexpr int LDA  = 144;
constexpr int LDBT = 272;
constexpr int LDBN = 144;
constexpr int A_HI = 0;
constexpr int A_LO = A_HI + 128 * LDA;       // 18432
constexpr int B_HI = A_LO + 128 * LDA;       // 36864
constexpr int B_LO = B_HI + 128 * LDBN;      // 55296 (max of both B layouts)
constexpr int GEMM_SMEM = B_LO + 128 * LDBN; // 73728
}  // namespace

__device__ float g_scratch[SCRATCH];

// ---------------------------------------------------------------------------
// warp-MMA helpers
// ---------------------------------------------------------------------------
__device__ __forceinline__ uint32_t smem_u32(const void* p) {
    uint32_t a;
    asm("{ .reg .u64 t; cvta.to.shared.u64 t, %1; cvt.u32.u64 %0, t; }" : "=r"(a) : "l"(p));
    return a;
}
__device__ __forceinline__ void ldsm_x4(uint32_t* r, uint32_t addr) {
    asm volatile("ldmatrix.sync.aligned.m8n8.x4.shared.b16 {%0,%1,%2,%3}, [%4];"
                 : "=r"(r[0]), "=r"(r[1]), "=r"(r[2]), "=r"(r[3]) : "r"(addr));
}
__device__ __forceinline__ void ldsm_x4t(uint32_t* r, uint32_t addr) {
    asm volatile("ldmatrix.sync.aligned.m8n8.x4.trans.shared.b16 {%0,%1,%2,%3}, [%4];"
                 : "=r"(r[0]), "=r"(r[1]), "=r"(r[2]), "=r"(r[3]) : "r"(addr));
}
__device__ __forceinline__ void mma_bf16(float* d, const uint32_t* a, const uint32_t* b) {
    asm volatile("mma.sync.aligned.m16n8k16.row.col.f32.bf16.bf16.f32 "
                 "{%0,%1,%2,%3}, {%4,%5,%6,%7}, {%8,%9}, {%0,%1,%2,%3};"
                 : "+f"(d[0]), "+f"(d[1]), "+f"(d[2]), "+f"(d[3])
                 : "r"(a[0]), "r"(a[1]), "r"(a[2]), "r"(a[3]), "r"(b[0]), "r"(b[1]));
}
__device__ __forceinline__ void split_store(char* hiB, char* loB, uint32_t off, float4 v) {
    __nv_bfloat162 h01 = __float22bfloat162_rn(make_float2(v.x, v.y));
    __nv_bfloat162 h23 = __float22bfloat162_rn(make_float2(v.z, v.w));
    float2 f01 = __bfloat1622float2(h01);
    float2 f23 = __bfloat1622float2(h23);
    __nv_bfloat162 l01 = __float22bfloat162_rn(make_float2(v.x - f01.x, v.y - f01.y));
    __nv_bfloat162 l23 = __float22bfloat162_rn(make_float2(v.z - f23.x, v.w - f23.y));
    *reinterpret_cast<__nv_bfloat162*>(hiB + off)     = h01;
    *reinterpret_cast<__nv_bfloat162*>(hiB + off + 4) = h23;
    *reinterpret_cast<__nv_bfloat162*>(loB + off)     = l01;
    *reinterpret_cast<__nv_bfloat162*>(loB + off + 4) = l23;
}
__device__ __forceinline__ float lrelu(float v) { return v >= 0.f ? v : v * NEG_SLOPE; }

// ---------------------------------------------------------------------------
// Multi-GEMM: for w in 0..NW-1: C_w[M,128] = A @ Wmath_w (+ bias_w)
//   MASK bit w == 1: W_w stored [k][n] (C = A@W), trans ldmatrix
//   MASK bit w == 0: W_w stored [n][k] (C = A@W^T), non-trans ldmatrix
// K processed in 2 chunks of 64 so two CTAs fit per SM.
// FIN: NW==1, epilogue computes out = lrelu(self/iso + (wsumh + A@W)*inv).
// ---------------------------------------------------------------------------
template <int NW, int MASK, bool FIN>
__global__ __launch_bounds__(256, 2)
void tc_gemm_multi(const float* __restrict__ A,
                   const float* __restrict__ Wa, const float* __restrict__ Wb,
                   const float* __restrict__ Wc, const float* __restrict__ Wd,
                   const float* __restrict__ ba, const float* __restrict__ bb,
                   const float* __restrict__ bc, const float* __restrict__ bd,
                   float* __restrict__ Ca, float* __restrict__ Cb,
                   float* __restrict__ Cc, float* __restrict__ Cd,
                   const float* __restrict__ wsumh, const float* __restrict__ denom,
                   const int* __restrict__ deg, const float* __restrict__ selfm,
                   const float* __restrict__ isom, int M)
{
    extern __shared__ char smem[];
    const uint32_t sb = smem_u32(smem);
    const int tid = threadIdx.x, wid = tid >> 5, lane = tid & 31;
    const int row0 = blockIdx.x * 128;
    const int mw = (wid & 3) * 32, nw = (wid >> 2) * 64;

    const float* Ws[4]   = {Wa, Wb, Wc, Wd};
    const float* Bias[4] = {ba, bb, bc, bd};
    float*       Cs[4]   = {Ca, Cb, Cc, Cd};

    const int ar = tid >> 1, acb = (tid & 1) * 32;
    const bool avalid = (row0 + ar) < M;

    // intra-warp fragment address components
    const uint32_t a_off  = (uint32_t)((mw + (lane & 15)) * LDA + ((lane >> 4) << 4));
    const uint32_t bt_off = (uint32_t)((((lane >> 3) & 1) * 8 + (lane & 7)) * LDBT
                                       + (nw + ((lane >> 4) << 3)) * 2);
    const uint32_t bn_off = (uint32_t)((nw + ((lane >> 4) << 3) + (lane & 7)) * LDBN
                                       + ((lane >> 3) & 1) * 16);

#pragma unroll
    for (int w = 0; w < NW; ++w) {
        const bool wkn = (MASK >> w) & 1;
        float acc[2][8][4];
#pragma unroll
        for (int mt = 0; mt < 2; ++mt)
#pragma unroll
            for (int nt = 0; nt < 8; ++nt)
#pragma unroll
                for (int j = 0; j < 4; ++j) acc[mt][nt][j] = 0.f;

#pragma unroll
        for (int c = 0; c < 2; ++c) {
            __syncthreads();   // protect smem reuse from previous mma phase

            // --- A chunk: cols [c*64, c*64+64) ---
            {
                const float4* ap = reinterpret_cast<const float4*>(
                    A + (size_t)(row0 + ar) * 128 + c * 64 + acb);
#pragma unroll
                for (int i = 0; i < 8; ++i) {
                    float4 v = avalid ? __ldg(ap + i) : make_float4(0.f, 0.f, 0.f, 0.f);
                    split_store(smem + A_HI, smem + A_LO, ar * LDA + (acb + i * 4) * 2, v);
                }
            }
            // --- B chunk ---
            if (wkn) {   // W stored [k][n]: tile rows = 64 k-rows of this chunk
                const int kr = tid >> 2, nb = (tid & 3) * 32;
                const float4* wp = reinterpret_cast<const float4*>(
                    Ws[w] + (size_t)(c * 64 + kr) * 128 + nb);
#pragma unroll
                for (int i = 0; i < 8; ++i) {
                    float4 v = __ldg(wp + i);
                    split_store(smem + B_HI, smem + B_LO, kr * LDBT + (nb + i * 4) * 2, v);
                }
            } else {     // W stored [n][k]: tile rows = 128 n-rows, cols = chunk k
                const int nr = tid >> 1, kb = (tid & 1) * 32;
                const float4* wp = reinterpret_cast<const float4*>(
                    Ws[w] + (size_t)nr * 128 + c * 64 + kb);
#pragma unroll
                for (int i = 0; i < 8; ++i) {
                    float4 v = __ldg(wp + i);
                    split_store(smem + B_HI, smem + B_LO, nr * LDBN + (kb + i * 4) * 2, v);
                }
            }
            __syncthreads();

            // --- MMA: 3 groups (hh, hl, lh) x 4 k16-steps ---
#pragma unroll
            for (int g = 0; g < 3; ++g) {
                const uint32_t abase = sb + (g == 2 ? A_LO : A_HI);
                const uint32_t bbase = sb + (g == 1 ? B_LO : B_HI);
#pragma unroll
                for (int kk = 0; kk < 4; ++kk) {
                    uint32_t a0[4], a1[4];
                    ldsm_x4(a0, abase + a_off + kk * 32);
                    ldsm_x4(a1, abase + a_off + 16 * LDA + kk * 32);
#pragma unroll
                    for (int p = 0; p < 4; ++p) {
                        uint32_t b4[4];
                        if (wkn)
                            ldsm_x4t(b4, bbase + bt_off + (uint32_t)(kk * 16 * LDBT + p * 32));
                        else
                            ldsm_x4(b4, bbase + bn_off + (uint32_t)(p * 16 * LDBN + kk * 32));
                        mma_bf16(acc[0][2 * p],     a0, b4);
                        mma_bf16(acc[0][2 * p + 1], a0, b4 + 2);
                        mma_bf16(acc[1][2 * p],     a1, b4);
                        mma_bf16(acc[1][2 * p + 1], a1, b4 + 2);
                    }
                }
            }
        }

        // --- epilogue ---
        const int rq = lane >> 2, c2 = (lane & 3) * 2;
        if (!FIN) {
            const float* bias = Bias[w];
            float* C = Cs[w];
#pragma unroll
            for (int mt = 0; mt < 2; ++mt) {
                const int r0 = row0 + mw + mt * 16 + rq;
#pragma unroll
                for (int nt = 0; nt < 8; ++nt) {
                    const int col = nw + nt * 8 + c2;
                    const float bx = bias ? __ldg(bias + col) : 0.f;
                    const float by = bias ? __ldg(bias + col + 1) : 0.f;
                    if (r0 < M)
                        *reinterpret_cast<float2*>(C + (size_t)r0 * 128 + col) =
                            make_float2(acc[mt][nt][0] + bx, acc[mt][nt][1] + by);
                    if (r0 + 8 < M)
                        *reinterpret_cast<float2*>(C + (size_t)(r0 + 8) * 128 + col) =
                            make_float2(acc[mt][nt][2] + bx, acc[mt][nt][3] + by);
                }
            }
        } else {
            float* C = Cs[0];
#pragma unroll
            for (int mt = 0; mt < 2; ++mt) {
                const int rA = row0 + mw + mt * 16 + rq;
                const int rB = rA + 8;
                float invA = 0.f, invB = 0.f;
                const float* smA = selfm;
                const float* smB = selfm;
                if (rA < M) {
                    invA = 1.0f / fmaxf(__ldg(denom + rA), 1e-30f);
                    if (__ldg(deg + rA) == 0) smA = isom;
                }
                if (rB < M) {
                    invB = 1.0f / fmaxf(__ldg(denom + rB), 1e-30f);
                    if (__ldg(deg + rB) == 0) smB = isom;
                }
#pragma unroll
                for (int nt = 0; nt < 8; ++nt) {
                    const int col = nw + nt * 8 + c2;
                    if (rA < M) {
                        float2 ws = *reinterpret_cast<const float2*>(wsumh + (size_t)rA * 128 + col);
                        float2 sm = *reinterpret_cast<const float2*>(smA   + (size_t)rA * 128 + col);
                        *reinterpret_cast<float2*>(C + (size_t)rA * 128 + col) = make_float2(
                            lrelu(sm.x + (ws.x + acc[mt][nt][0]) * invA),
                            lrelu(sm.y + (ws.y + acc[mt][nt][1]) * invA));
                    }
                    if (rB < M) {
                        float2 ws = *reinterpret_cast<const float2*>(wsumh + (size_t)rB * 128 + col);
                        float2 sm = *reinterpret_cast<const float2*>(smB   + (size_t)rB * 128 + col);
                        *reinterpret_cast<float2*>(C + (size_t)rB * 128 + col) = make_float2(
                            lrelu(sm.x + (ws.x + acc[mt][nt][2]) * invB),
                            lrelu(sm.y + (ws.y + acc[mt][nt][3]) * invB));
                    }
                }
            }
        }
    }
}

// ---------------------------------------------------------------------------
// small helpers
// ---------------------------------------------------------------------------
__global__ void zero_int_kernel(int* p, int n)
{
    int i = blockIdx.x * blockDim.x + threadIdx.x;
    if (i < n) p[i] = 0;
}

__global__ void deg_kernel(const int* __restrict__ dst, int* __restrict__ deg)
{
    int e = blockIdx.x * blockDim.x + threadIdx.x;
    if (e < NE) atomicAdd(deg + dst[e], 1);
}

__global__ void init_layer_kernel(float* __restrict__ wsumh, float* __restrict__ sbuf,
                                  float* __restrict__ denom, unsigned int* __restrict__ smax)
{
    size_t i = (size_t)blockIdx.x * blockDim.x + threadIdx.x;
    if (i < ND) { wsumh[i] = 0.f; sbuf[i] = 0.f; }
    if (i < NN) { denom[i] = 0.f; smax[i] = 0u; }
}

// ---------------------------------------------------------------------------
// pass 1: per-edge score + segment max (one warp per edge)
// ---------------------------------------------------------------------------
__global__ __launch_bounds__(256) void pass1_kernel(
    const float* __restrict__ h, const float* __restrict__ hW1,
    const float* __restrict__ g, const float* __restrict__ ef,
    const int* __restrict__ src, const int* __restrict__ dst,
    float* __restrict__ score, unsigned int* __restrict__ smax)
{
    int gt = blockIdx.x * blockDim.x + threadIdx.x;
    int e = gt >> 5;
    if (e >= NE) return;
    int lane = gt & 31;
    int s = __ldg(src + e), d = __ldg(dst + e);

    float4 hd = __ldg(reinterpret_cast<const float4*>(h)   + d * 32 + lane);
    float4 hw = __ldg(reinterpret_cast<const float4*>(hW1) + s * 32 + lane);
    float4 gd = __ldg(reinterpret_cast<const float4*>(g)   + d * 32 + lane);
    float4 ev = __ldg(reinterpret_cast<const float4*>(ef)  + (size_t)e * 32 + lane);

    float p = hd.x * hw.x + hd.y * hw.y + hd.z * hw.z + hd.w * hw.w
            + gd.x * ev.x + gd.y * ev.y + gd.z * ev.z + gd.w * ev.w;
#pragma unroll
    for (int o = 16; o > 0; o >>= 1) p += __shfl_xor_sync(0xffffffffu, p, o);

    if (lane == 0) {
        score[e] = p;
        unsigned u = __float_as_uint(p);
        u = (u & 0x80000000u) ? ~u : (u | 0x80000000u);
        atomicMax(smax + d, u);
    }
}

// ---------------------------------------------------------------------------
// pass 2: w = exp(score - smax); scatter w*hW1[src], w*efeat via red.v4
// ---------------------------------------------------------------------------
__device__ __forceinline__ void red4(float* p, float a, float b, float c, float d)
{
    asm volatile("red.global.add.v4.f32 [%0], {%1,%2,%3,%4};"
                 :: "l"(p), "f"(a), "f"(b), "f"(c), "f"(d) : "memory");
}

__global__ __launch_bounds__(256) void pass2_kernel(
    const float* __restrict__ hW1, const float* __restrict__ ef,
    const int* __restrict__ src, const int* __restrict__ dst,
    const float* __restrict__ score, const unsigned int* __restrict__ smax,
    float* __restrict__ denom, float* __restrict__ wsumh, float* __restrict__ sbuf)
{
    int gt = blockIdx.x * blockDim.x + threadIdx.x;
    int e = gt >> 5;
    if (e >= NE) return;
    int lane = gt & 31;
    int s = __ldg(src + e), d = __ldg(dst + e);

    unsigned mu = __ldg(smax + d);
    float mx = (mu & 0x80000000u) ? __uint_as_float(mu ^ 0x80000000u)
                                  : __uint_as_float(~mu);
    float w = __expf(__ldg(score + e) - mx);
    if (lane == 0) atomicAdd(denom + d, w);

    float4 hw = __ldg(reinterpret_cast<const float4*>(hW1) + s * 32 + lane);
    float4 ev = __ldg(reinterpret_cast<const float4*>(ef)  + (size_t)e * 32 + lane);

    red4(wsumh + (size_t)d * 128 + lane * 4, w * hw.x, w * hw.y, w * hw.z, w * hw.w);
    red4(sbuf  + (size_t)d * 128 + lane * 4, w * ev.x, w * ev.y, w * ev.z, w * ev.w);
}

// ---------------------------------------------------------------------------
// launch
// ---------------------------------------------------------------------------
extern "C" void kernel_launch(void* const* d_in, const int* in_sizes, int n_in,
                              void* d_out, int out_size)
{
    const float* node = (const float*)d_in[0];
    const float* ef   = (const float*)d_in[1];
    const int*   src  = (const int*)d_in[2];
    const int*   dst  = (const int*)d_in[3];
    const float* W1[2] = {(const float*)d_in[4],  (const float*)d_in[10]};
    const float* B1[2] = {(const float*)d_in[5],  (const float*)d_in[11]};
    const float* W2[2] = {(const float*)d_in[6],  (const float*)d_in[12]};
    const float* B2[2] = {(const float*)d_in[7],  (const float*)d_in[13]};
    const float* W3[2] = {(const float*)d_in[8],  (const float*)d_in[14]};
    const float* B3[2] = {(const float*)d_in[9],  (const float*)d_in[15]};

    float* base = nullptr;
    cudaGetSymbolAddress((void**)&base, g_scratch);

    float*        hW1   = base + O_HW1;
    float*        g     = base + O_G;
    float*        selfm = base + O_SELF;
    float*        isom  = base + O_ISO;
    float*        wsumh = base + O_WSUM;
    float*        sbuf  = base + O_S;
    float*        h1    = base + O_H1;
    float*        score = base + O_SCORE;
    unsigned int* smax  = (unsigned int*)(base + O_SMAX);
    float*        denom = base + O_DEN;
    int*          deg   = (int*)(base + O_DEG);

    // fused 4-GEMM: weights {W1 [k][n], W1 as [n][k] (transposed math), W2, W3}
    auto* kf4 = &tc_gemm_multi<4, 0b1101, false>;
    auto* kf1 = &tc_gemm_multi<1, 0b1,    true>;
    cudaFuncSetAttribute(kf4, cudaFuncAttributeMaxDynamicSharedMemorySize, GEMM_SMEM);
    cudaFuncSetAttribute(kf1, cudaFuncAttributeMaxDynamicSharedMemorySize, GEMM_SMEM);

    zero_int_kernel<<<(NN + 255) / 256, 256>>>(deg, NN);
    deg_kernel<<<(NE + 255) / 256, 256>>>(dst, deg);

    const int gemmGrid = (NN + 127) / 128;                      // 391
    const int edgeGrid = (int)(((size_t)NE * 32 + 255) / 256);  // 75000
    const int initGrid = (int)((ND + 255) / 256);

    const float* h = node;
    float* out_l[2] = {h1, (float*)d_out};

    for (int l = 0; l < 2; ++l) {
        init_layer_kernel<<<initGrid, 256>>>(wsumh, sbuf, denom, smax);

        kf4<<<gemmGrid, 256, GEMM_SMEM>>>(
            h, W1[l], W1[l], W2[l], W3[l],
            B1[l], nullptr, B2[l], B3[l],
            hW1, g, selfm, isom,
            nullptr, nullptr, nullptr, nullptr, nullptr, NN);

        pass1_kernel<<<edgeGrid, 256>>>(h, hW1, g, ef, src, dst, score, smax);
        pass2_kernel<<<edgeGrid, 256>>>(hW1, ef, src, dst, score, smax, denom, wsumh, sbuf);

        // out = lrelu(self/iso + (wsumh + sbuf@W1)/denom)  — GEMM + finalize fused
        kf1<<<gemmGrid, 256, GEMM_SMEM>>>(
            sbuf, W1[l], W1[l], W1[l], W1[l],
            nullptr, nullptr, nullptr, nullptr,
            out_l[l], nullptr, nullptr, nullptr,
            wsumh, denom, deg, selfm, isom, NN);

        h = h1;
    }
}

// round 7
// speedup vs baseline: 1.3263x; 1.3263x over previous
#include <cuda_runtime.h>
#include <cuda_bf16.h>
#include <cstdint>

// ---------------------------------------------------------------------------
// RelGAT restructured:
//   score_e = <h[dst], hW1[src]> + <g[dst], efeat_e>,  g = h@W1^T, hW1 = h@W1+b1
//   neigh_d = ( sum w_e hW1[src] + (sum w_e efeat_e)@W1 ) / denom
// Round 7:
//  - softmax max-subtraction removed (exact rescaling; scores << 88) ->
//    single fused edge pass (score + exp + scatter), pass1 deleted.
//  - isom GEMM removed; rare deg==0 rows patched by a fix-up kernel.
//  - GEMM reverted to the proven R5 single-GEMM mma.sync bf16x3 kernel.
// ---------------------------------------------------------------------------

namespace {
constexpr int    NN  = 50000;
constexpr int    NE  = 600000;
constexpr size_t ND  = (size_t)NN * 128;
constexpr float  NEG_SLOPE = 0.22916666666666666f;

constexpr size_t O_HW1  = 0;
constexpr size_t O_G    = 1 * ND;
constexpr size_t O_SELF = 2 * ND;
constexpr size_t O_WSUM = 3 * ND;
constexpr size_t O_S    = 4 * ND;
constexpr size_t O_SW1  = 5 * ND;
constexpr size_t O_H1   = 6 * ND;
constexpr size_t O_DEN  = 7 * ND;           // NN
constexpr size_t O_DEG  = O_DEN + NN;       // NN (int)
constexpr size_t SCRATCH = O_DEG + NN;

// R5 GEMM smem layout (bytes); padded rows: 128 bf16 + 8 pad = 272 B/row.
constexpr int LDTB       = 272;
constexpr int TILE_BYTES = 128 * LDTB;     // 34816
constexpr int SM_BIAS = 0;
constexpr int SA_HI = 512;
constexpr int SA_LO = SA_HI + TILE_BYTES;
constexpr int SB_HI = SA_LO + TILE_BYTES;
constexpr int SB_LO = SB_HI + TILE_BYTES;
constexpr int GEMM_SMEM = SB_LO + TILE_BYTES;   // 139,776 B
}  // namespace

__device__ float g_scratch[SCRATCH];

// ---------------------------------------------------------------------------
// warp-MMA helpers
// ---------------------------------------------------------------------------
__device__ __forceinline__ uint32_t smem_u32(const void* p) {
    uint32_t a;
    asm("{ .reg .u64 t; cvta.to.shared.u64 t, %1; cvt.u32.u64 %0, t; }" : "=r"(a) : "l"(p));
    return a;
}
__device__ __forceinline__ void ldsm_x4(uint32_t* r, uint32_t addr) {
    asm volatile("ldmatrix.sync.aligned.m8n8.x4.shared.b16 {%0,%1,%2,%3}, [%4];"
                 : "=r"(r[0]), "=r"(r[1]), "=r"(r[2]), "=r"(r[3]) : "r"(addr));
}
__device__ __forceinline__ void ldsm_x2t(uint32_t* r, uint32_t addr) {
    asm volatile("ldmatrix.sync.aligned.m8n8.x2.trans.shared.b16 {%0,%1}, [%2];"
                 : "=r"(r[0]), "=r"(r[1]) : "r"(addr));
}
__device__ __forceinline__ void ldsm_x2(uint32_t* r, uint32_t addr) {
    asm volatile("ldmatrix.sync.aligned.m8n8.x2.shared.b16 {%0,%1}, [%2];"
                 : "=r"(r[0]), "=r"(r[1]) : "r"(addr));
}
__device__ __forceinline__ void mma_bf16(float* d, const uint32_t* a, const uint32_t* b) {
    asm volatile("mma.sync.aligned.m16n8k16.row.col.f32.bf16.bf16.f32 "
                 "{%0,%1,%2,%3}, {%4,%5,%6,%7}, {%8,%9}, {%0,%1,%2,%3};"
                 : "+f"(d[0]), "+f"(d[1]), "+f"(d[2]), "+f"(d[3])
                 : "r"(a[0]), "r"(a[1]), "r"(a[2]), "r"(a[3]), "r"(b[0]), "r"(b[1]));
}
__device__ __forceinline__ void split_store(char* hiB, char* loB, uint32_t off, float4 v) {
    __nv_bfloat162 h01 = __float22bfloat162_rn(make_float2(v.x, v.y));
    __nv_bfloat162 h23 = __float22bfloat162_rn(make_float2(v.z, v.w));
    float2 f01 = __bfloat1622float2(h01);
    float2 f23 = __bfloat1622float2(h23);
    __nv_bfloat162 l01 = __float22bfloat162_rn(make_float2(v.x - f01.x, v.y - f01.y));
    __nv_bfloat162 l23 = __float22bfloat162_rn(make_float2(v.z - f23.x, v.w - f23.y));
    *reinterpret_cast<__nv_bfloat162*>(hiB + off)     = h01;
    *reinterpret_cast<__nv_bfloat162*>(hiB + off + 4) = h23;
    *reinterpret_cast<__nv_bfloat162*>(loB + off)     = l01;
    *reinterpret_cast<__nv_bfloat162*>(loB + off + 4) = l23;
}
__device__ __forceinline__ float lrelu(float v) { return v >= 0.f ? v : v * NEG_SLOPE; }

// ---------------------------------------------------------------------------
// tensor-core GEMM (R5, proven): C[M,128] = A[M,128] @ Wmath + bias
// WKN=1: Wmath = W stored [k][n] (C=A@W, trans ldmatrix)
// WKN=0: Wmath = W^T, W stored [n][k] (C=A@W^T, non-trans ldmatrix)
// ---------------------------------------------------------------------------
template <int WKN>
__global__ __launch_bounds__(256, 1)
void tc_gemm(const float* __restrict__ A, const float* __restrict__ W,
             const float* __restrict__ bias, float* __restrict__ C, int M)
{
    extern __shared__ char smem[];
    const uint32_t sb = smem_u32(smem);
    const int tid = threadIdx.x, wid = tid >> 5, lane = tid & 31;
    const int row0 = blockIdx.x * 128;

    if (tid < 128)
        reinterpret_cast<float*>(smem + SM_BIAS)[tid] = bias ? bias[tid] : 0.f;

    {
        const int r = tid >> 1, ch = (tid & 1) << 6;
        const bool valid = (row0 + r) < M;
        const float4* ap = reinterpret_cast<const float4*>(A + (size_t)(row0 + r) * 128 + ch);
#pragma unroll
        for (int i = 0; i < 16; ++i) {
            float4 v = valid ? __ldg(ap + i) : make_float4(0.f, 0.f, 0.f, 0.f);
            split_store(smem + SA_HI, smem + SA_LO, r * LDTB + (ch + i * 4) * 2, v);
        }
    }
    {
        const int r = tid >> 1, ch = (tid & 1) << 6;
        const float4* wp = reinterpret_cast<const float4*>(W + (size_t)r * 128 + ch);
#pragma unroll
        for (int i = 0; i < 16; ++i) {
            float4 v = __ldg(wp + i);
            split_store(smem + SB_HI, smem + SB_LO, r * LDTB + (ch + i * 4) * 2, v);
        }
    }
    __syncthreads();

    const int mw = (wid & 3) * 32;
    const int nw = (wid >> 2) * 64;

    float acc[2][8][4];
#pragma unroll
    for (int mt = 0; mt < 2; ++mt)
#pragma unroll
        for (int nt = 0; nt < 8; ++nt)
#pragma unroll
            for (int j = 0; j < 4; ++j) acc[mt][nt][j] = 0.f;

    const uint32_t a_row_off = (mw + (lane & 15)) * LDTB + ((lane >> 4) << 3) * 2;
    const uint32_t bt_row    = (lane & 15) * LDTB;
    const uint32_t bn_off    = (lane & 7) * LDTB + (((lane >> 3) & 1) << 3) * 2;

#pragma unroll
    for (int g = 0; g < 3; ++g) {
        const uint32_t abase = sb + (g == 2 ? SA_LO : SA_HI);
        const uint32_t bbase = sb + (g == 1 ? SB_LO : SB_HI);
#pragma unroll
        for (int kk = 0; kk < 8; ++kk) {
            uint32_t a[2][4];
            ldsm_x4(a[0], abase + a_row_off + kk * 32);
            ldsm_x4(a[1], abase + a_row_off + 16 * LDTB + kk * 32);
            uint32_t b[8][2];
#pragma unroll
            for (int nt = 0; nt < 8; ++nt) {
                if (WKN)
                    ldsm_x2t(b[nt], bbase + kk * 16 * LDTB + bt_row + (nw + nt * 8) * 2);
                else
                    ldsm_x2(b[nt], bbase + (nw + nt * 8) * LDTB + bn_off + kk * 32);
            }
#pragma unroll
            for (int mt = 0; mt < 2; ++mt)
#pragma unroll
                for (int nt = 0; nt < 8; ++nt)
                    mma_bf16(acc[mt][nt], a[mt], b[nt]);
        }
    }

    const float* bs = reinterpret_cast<const float*>(smem + SM_BIAS);
    const int rq = lane >> 2, c2 = (lane & 3) * 2;
#pragma unroll
    for (int mt = 0; mt < 2; ++mt) {
        const int r0 = row0 + mw + mt * 16 + rq;
#pragma unroll
        for (int nt = 0; nt < 8; ++nt) {
            const int col = nw + nt * 8 + c2;
            const float bx = bs[col], by = bs[col + 1];
            if (r0 < M)
                *reinterpret_cast<float2*>(C + (size_t)r0 * 128 + col) =
                    make_float2(acc[mt][nt][0] + bx, acc[mt][nt][1] + by);
            if (r0 + 8 < M)
                *reinterpret_cast<float2*>(C + (size_t)(r0 + 8) * 128 + col) =
                    make_float2(acc[mt][nt][2] + bx, acc[mt][nt][3] + by);
        }
    }
}

// ---------------------------------------------------------------------------
// small helpers
// ---------------------------------------------------------------------------
__global__ void zero_int_kernel(int* p, int n)
{
    int i = blockIdx.x * blockDim.x + threadIdx.x;
    if (i < n) p[i] = 0;
}

__global__ void deg_kernel(const int* __restrict__ dst, int* __restrict__ deg)
{
    int e = blockIdx.x * blockDim.x + threadIdx.x;
    if (e < NE) atomicAdd(deg + dst[e], 1);
}

__global__ void init_layer_kernel(float* __restrict__ wsumh, float* __restrict__ sbuf,
                                  float* __restrict__ denom)
{
    size_t i = (size_t)blockIdx.x * blockDim.x + threadIdx.x;
    if (i < ND) { wsumh[i] = 0.f; sbuf[i] = 0.f; }
    if (i < NN) denom[i] = 0.f;
}

// ---------------------------------------------------------------------------
// fused edge pass (one warp per edge):
//   p = <h[dst], hW1[src]> + <g[dst], ef_e>;  w = exp(p)   (no max: exact rescale)
//   denom[d] += w;  wsumh[d] += w*hW1[src];  sbuf[d] += w*ef_e
// ---------------------------------------------------------------------------
__device__ __forceinline__ void red4(float* p, float a, float b, float c, float d)
{
    asm volatile("red.global.add.v4.f32 [%0], {%1,%2,%3,%4};"
                 :: "l"(p), "f"(a), "f"(b), "f"(c), "f"(d) : "memory");
}

__global__ __launch_bounds__(256) void edge_kernel(
    const float* __restrict__ h, const float* __restrict__ hW1,
    const float* __restrict__ g, const float* __restrict__ ef,
    const int* __restrict__ src, const int* __restrict__ dst,
    float* __restrict__ denom, float* __restrict__ wsumh, float* __restrict__ sbuf)
{
    int gt = blockIdx.x * blockDim.x + threadIdx.x;
    int e = gt >> 5;
    if (e >= NE) return;
    int lane = gt & 31;
    int s = __ldg(src + e), d = __ldg(dst + e);

    float4 hd = __ldg(reinterpret_cast<const float4*>(h)   + d * 32 + lane);
    float4 hw = __ldg(reinterpret_cast<const float4*>(hW1) + s * 32 + lane);
    float4 gd = __ldg(reinterpret_cast<const float4*>(g)   + d * 32 + lane);
    float4 ev = __ldg(reinterpret_cast<const float4*>(ef)  + (size_t)e * 32 + lane);

    float p = hd.x * hw.x + hd.y * hw.y + hd.z * hw.z + hd.w * hw.w
            + gd.x * ev.x + gd.y * ev.y + gd.z * ev.z + gd.w * ev.w;
#pragma unroll
    for (int o = 16; o > 0; o >>= 1) p += __shfl_xor_sync(0xffffffffu, p, o);

    float w = __expf(p);
    if (lane == 0) atomicAdd(denom + d, w);

    red4(wsumh + (size_t)d * 128 + lane * 4, w * hw.x, w * hw.y, w * hw.z, w * hw.w);
    red4(sbuf  + (size_t)d * 128 + lane * 4, w * ev.x, w * ev.y, w * ev.z, w * ev.w);
}

// ---------------------------------------------------------------------------
// finalize: out = lrelu(selfm + (wsumh + sW1)/max(denom,1e-30))
// deg==0 rows produce lrelu(selfm) here and are patched by fixup_iso after.
// ---------------------------------------------------------------------------
__global__ __launch_bounds__(256) void finalize_kernel(
    const float* __restrict__ wsumh, const float* __restrict__ sW1,
    const float* __restrict__ denom, const float* __restrict__ selfm,
    float* __restrict__ out)
{
    int i = blockIdx.x * blockDim.x + threadIdx.x;
    if (i >= NN * 32) return;
    int n = i >> 5;

    float4 ws = __ldg(reinterpret_cast<const float4*>(wsumh) + i);
    float4 sv = __ldg(reinterpret_cast<const float4*>(sW1)   + i);
    float inv = 1.0f / fmaxf(__ldg(denom + n), 1e-30f);
    float4 sm = __ldg(reinterpret_cast<const float4*>(selfm) + i);

    float4 r;
    r.x = lrelu(sm.x + (ws.x + sv.x) * inv);
    r.y = lrelu(sm.y + (ws.y + sv.y) * inv);
    r.z = lrelu(sm.z + (ws.z + sv.z) * inv);
    r.w = lrelu(sm.w + (ws.w + sv.w) * inv);
    reinterpret_cast<float4*>(out)[i] = r;
}

// ---------------------------------------------------------------------------
// fixup: for the rare deg==0 nodes, out = lrelu(h@W3 + b3)
// one warp per node; early exit on deg != 0.
// ---------------------------------------------------------------------------
__global__ __launch_bounds__(256) void fixup_iso(
    const float* __restrict__ h, const float* __restrict__ W3,
    const float* __restrict__ b3, const int* __restrict__ deg,
    float* __restrict__ out)
{
    int n = blockIdx.x * 8 + (threadIdx.x >> 5);
    if (n >= NN) return;
    if (__ldg(deg + n) != 0) return;
    int lane = threadIdx.x & 31;
    int c0 = lane * 4;

    float acc0 = __ldg(b3 + c0), acc1 = __ldg(b3 + c0 + 1);
    float acc2 = __ldg(b3 + c0 + 2), acc3 = __ldg(b3 + c0 + 3);
    for (int k = 0; k < 128; ++k) {
        float hv = __ldg(h + (size_t)n * 128 + k);
        const float* wr = W3 + (size_t)k * 128 + c0;
        acc0 += hv * __ldg(wr);
        acc1 += hv * __ldg(wr + 1);
        acc2 += hv * __ldg(wr + 2);
        acc3 += hv * __ldg(wr + 3);
    }
    float4 r = make_float4(lrelu(acc0), lrelu(acc1), lrelu(acc2), lrelu(acc3));
    *reinterpret_cast<float4*>(out + (size_t)n * 128 + c0) = r;
}

// ---------------------------------------------------------------------------
// launch
// ---------------------------------------------------------------------------
extern "C" void kernel_launch(void* const* d_in, const int* in_sizes, int n_in,
                              void* d_out, int out_size)
{
    const float* node = (const float*)d_in[0];
    const float* ef   = (const float*)d_in[1];
    const int*   src  = (const int*)d_in[2];
    const int*   dst  = (const int*)d_in[3];
    const float* W1[2] = {(const float*)d_in[4],  (const float*)d_in[10]};
    const float* B1[2] = {(const float*)d_in[5],  (const float*)d_in[11]};
    const float* W2[2] = {(const float*)d_in[6],  (const float*)d_in[12]};
    const float* B2[2] = {(const float*)d_in[7],  (const float*)d_in[13]};
    const float* W3[2] = {(const float*)d_in[8],  (const float*)d_in[14]};
    const float* B3[2] = {(const float*)d_in[9],  (const float*)d_in[15]};

    float* base = nullptr;
    cudaGetSymbolAddress((void**)&base, g_scratch);

    float* hW1   = base + O_HW1;
    float* g     = base + O_G;
    float* selfm = base + O_SELF;
    float* wsumh = base + O_WSUM;
    float* sbuf  = base + O_S;
    float* sW1   = base + O_SW1;
    float* h1    = base + O_H1;
    float* denom = base + O_DEN;
    int*   deg   = (int*)(base + O_DEG);

    cudaFuncSetAttribute(tc_gemm<1>, cudaFuncAttributeMaxDynamicSharedMemorySize, GEMM_SMEM);
    cudaFuncSetAttribute(tc_gemm<0>, cudaFuncAttributeMaxDynamicSharedMemorySize, GEMM_SMEM);

    zero_int_kernel<<<(NN + 255) / 256, 256>>>(deg, NN);
    deg_kernel<<<(NE + 255) / 256, 256>>>(dst, deg);

    const int gemmGrid = (NN + 127) / 128;                      // 391
    const int edgeGrid = (int)(((size_t)NE * 32 + 255) / 256);  // 75000
    const int initGrid = (int)((ND + 255) / 256);

    const float* h = node;
    float* out_l[2] = {h1, (float*)d_out};

    for (int l = 0; l < 2; ++l) {
        init_layer_kernel<<<initGrid, 256>>>(wsumh, sbuf, denom);

        tc_gemm<1><<<gemmGrid, 256, GEMM_SMEM>>>(h, W1[l], B1[l], hW1,   NN);
        tc_gemm<0><<<gemmGrid, 256, GEMM_SMEM>>>(h, W1[l], nullptr, g,   NN);  // h @ W1^T
        tc_gemm<1><<<gemmGrid, 256, GEMM_SMEM>>>(h, W2[l], B2[l], selfm, NN);

        edge_kernel<<<edgeGrid, 256>>>(h, hW1, g, ef, src, dst, denom, wsumh, sbuf);

        tc_gemm<1><<<gemmGrid, 256, GEMM_SMEM>>>(sbuf, W1[l], nullptr, sW1, NN);

        finalize_kernel<<<(NN * 32 + 255) / 256, 256>>>(wsumh, sW1, denom, selfm, out_l[l]);
        fixup_iso<<<(NN + 7) / 8, 256>>>(h, W3[l], B3[l], deg, out_l[l]);

        h = h1;
    }
}

// round 8
// speedup vs baseline: 1.5857x; 1.1956x over previous
#include <cuda_runtime.h>
#include <cuda_bf16.h>
#include <cstdint>

// ---------------------------------------------------------------------------
// RelGAT restructured:
//   score_e = <h[dst], hW1[src]> + <g[dst], efeat_e>,  g = h@W1^T, hW1 = h@W1+b1
//   neigh_d = ( sum w_e hW1[src] + (sum w_e efeat_e)@W1 ) / denom
// Round 8: dst-CSR built once (graph identical across layers); edge
// aggregation is one warp per node with register accumulators -> zero atomics,
// no zero-init pass. Softmax max-subtraction removed (exact rescale).
// GEMMs: R5 mma.sync bf16x3 kernel (unchanged).
// ---------------------------------------------------------------------------

namespace {
constexpr int    NN  = 50000;
constexpr int    NE  = 600000;
constexpr size_t ND  = (size_t)NN * 128;
constexpr float  NEG_SLOPE = 0.22916666666666666f;

constexpr size_t O_HW1  = 0;
constexpr size_t O_G    = 1 * ND;
constexpr size_t O_SELF = 2 * ND;
constexpr size_t O_WSUM = 3 * ND;
constexpr size_t O_S    = 4 * ND;
constexpr size_t O_SW1  = 5 * ND;
constexpr size_t O_H1   = 6 * ND;
constexpr size_t O_DEN    = 7 * ND;            // NN floats
constexpr size_t O_DEG    = O_DEN + NN;        // NN ints
constexpr size_t O_ROWPTR = O_DEG + NN;        // NN+1 ints
constexpr size_t O_WPOS   = O_ROWPTR + NN + 1; // NN ints
constexpr size_t O_CSRS   = O_WPOS + NN;       // NE ints (src per slot)
constexpr size_t O_CSRE   = O_CSRS + NE;       // NE ints (edge id per slot)
constexpr size_t SCRATCH  = O_CSRE + NE;

// R5 GEMM smem layout (bytes); padded rows: 128 bf16 + 8 pad = 272 B/row.
constexpr int LDTB       = 272;
constexpr int TILE_BYTES = 128 * LDTB;     // 34816
constexpr int SM_BIAS = 0;
constexpr int SA_HI = 512;
constexpr int SA_LO = SA_HI + TILE_BYTES;
constexpr int SB_HI = SA_LO + TILE_BYTES;
constexpr int SB_LO = SB_HI + TILE_BYTES;
constexpr int GEMM_SMEM = SB_LO + TILE_BYTES;   // 139,776 B
}  // namespace

__device__ float g_scratch[SCRATCH];

// ---------------------------------------------------------------------------
// warp-MMA helpers
// ---------------------------------------------------------------------------
__device__ __forceinline__ uint32_t smem_u32(const void* p) {
    uint32_t a;
    asm("{ .reg .u64 t; cvta.to.shared.u64 t, %1; cvt.u32.u64 %0, t; }" : "=r"(a) : "l"(p));
    return a;
}
__device__ __forceinline__ void ldsm_x4(uint32_t* r, uint32_t addr) {
    asm volatile("ldmatrix.sync.aligned.m8n8.x4.shared.b16 {%0,%1,%2,%3}, [%4];"
                 : "=r"(r[0]), "=r"(r[1]), "=r"(r[2]), "=r"(r[3]) : "r"(addr));
}
__device__ __forceinline__ void ldsm_x2t(uint32_t* r, uint32_t addr) {
    asm volatile("ldmatrix.sync.aligned.m8n8.x2.trans.shared.b16 {%0,%1}, [%2];"
                 : "=r"(r[0]), "=r"(r[1]) : "r"(addr));
}
__device__ __forceinline__ void ldsm_x2(uint32_t* r, uint32_t addr) {
    asm volatile("ldmatrix.sync.aligned.m8n8.x2.shared.b16 {%0,%1}, [%2];"
                 : "=r"(r[0]), "=r"(r[1]) : "r"(addr));
}
__device__ __forceinline__ void mma_bf16(float* d, const uint32_t* a, const uint32_t* b) {
    asm volatile("mma.sync.aligned.m16n8k16.row.col.f32.bf16.bf16.f32 "
                 "{%0,%1,%2,%3}, {%4,%5,%6,%7}, {%8,%9}, {%0,%1,%2,%3};"
                 : "+f"(d[0]), "+f"(d[1]), "+f"(d[2]), "+f"(d[3])
                 : "r"(a[0]), "r"(a[1]), "r"(a[2]), "r"(a[3]), "r"(b[0]), "r"(b[1]));
}
__device__ __forceinline__ void split_store(char* hiB, char* loB, uint32_t off, float4 v) {
    __nv_bfloat162 h01 = __float22bfloat162_rn(make_float2(v.x, v.y));
    __nv_bfloat162 h23 = __float22bfloat162_rn(make_float2(v.z, v.w));
    float2 f01 = __bfloat1622float2(h01);
    float2 f23 = __bfloat1622float2(h23);
    __nv_bfloat162 l01 = __float22bfloat162_rn(make_float2(v.x - f01.x, v.y - f01.y));
    __nv_bfloat162 l23 = __float22bfloat162_rn(make_float2(v.z - f23.x, v.w - f23.y));
    *reinterpret_cast<__nv_bfloat162*>(hiB + off)     = h01;
    *reinterpret_cast<__nv_bfloat162*>(hiB + off + 4) = h23;
    *reinterpret_cast<__nv_bfloat162*>(loB + off)     = l01;
    *reinterpret_cast<__nv_bfloat162*>(loB + off + 4) = l23;
}
__device__ __forceinline__ float lrelu(float v) { return v >= 0.f ? v : v * NEG_SLOPE; }

// ---------------------------------------------------------------------------
// tensor-core GEMM (R5, proven): C[M,128] = A[M,128] @ Wmath + bias
// WKN=1: Wmath = W stored [k][n] (C=A@W).  WKN=0: Wmath = W^T, W stored [n][k].
// ---------------------------------------------------------------------------
template <int WKN>
__global__ __launch_bounds__(256, 1)
void tc_gemm(const float* __restrict__ A, const float* __restrict__ W,
             const float* __restrict__ bias, float* __restrict__ C, int M)
{
    extern __shared__ char smem[];
    const uint32_t sb = smem_u32(smem);
    const int tid = threadIdx.x, wid = tid >> 5, lane = tid & 31;
    const int row0 = blockIdx.x * 128;

    if (tid < 128)
        reinterpret_cast<float*>(smem + SM_BIAS)[tid] = bias ? bias[tid] : 0.f;

    {
        const int r = tid >> 1, ch = (tid & 1) << 6;
        const bool valid = (row0 + r) < M;
        const float4* ap = reinterpret_cast<const float4*>(A + (size_t)(row0 + r) * 128 + ch);
#pragma unroll
        for (int i = 0; i < 16; ++i) {
            float4 v = valid ? __ldg(ap + i) : make_float4(0.f, 0.f, 0.f, 0.f);
            split_store(smem + SA_HI, smem + SA_LO, r * LDTB + (ch + i * 4) * 2, v);
        }
    }
    {
        const int r = tid >> 1, ch = (tid & 1) << 6;
        const float4* wp = reinterpret_cast<const float4*>(W + (size_t)r * 128 + ch);
#pragma unroll
        for (int i = 0; i < 16; ++i) {
            float4 v = __ldg(wp + i);
            split_store(smem + SB_HI, smem + SB_LO, r * LDTB + (ch + i * 4) * 2, v);
        }
    }
    __syncthreads();

    const int mw = (wid & 3) * 32;
    const int nw = (wid >> 2) * 64;

    float acc[2][8][4];
#pragma unroll
    for (int mt = 0; mt < 2; ++mt)
#pragma unroll
        for (int nt = 0; nt < 8; ++nt)
#pragma unroll
            for (int j = 0; j < 4; ++j) acc[mt][nt][j] = 0.f;

    const uint32_t a_row_off = (mw + (lane & 15)) * LDTB + ((lane >> 4) << 3) * 2;
    const uint32_t bt_row    = (lane & 15) * LDTB;
    const uint32_t bn_off    = (lane & 7) * LDTB + (((lane >> 3) & 1) << 3) * 2;

#pragma unroll
    for (int g = 0; g < 3; ++g) {
        const uint32_t abase = sb + (g == 2 ? SA_LO : SA_HI);
        const uint32_t bbase = sb + (g == 1 ? SB_LO : SB_HI);
#pragma unroll
        for (int kk = 0; kk < 8; ++kk) {
            uint32_t a[2][4];
            ldsm_x4(a[0], abase + a_row_off + kk * 32);
            ldsm_x4(a[1], abase + a_row_off + 16 * LDTB + kk * 32);
            uint32_t b[8][2];
#pragma unroll
            for (int nt = 0; nt < 8; ++nt) {
                if (WKN)
                    ldsm_x2t(b[nt], bbase + kk * 16 * LDTB + bt_row + (nw + nt * 8) * 2);
                else
                    ldsm_x2(b[nt], bbase + (nw + nt * 8) * LDTB + bn_off + kk * 32);
            }
#pragma unroll
            for (int mt = 0; mt < 2; ++mt)
#pragma unroll
                for (int nt = 0; nt < 8; ++nt)
                    mma_bf16(acc[mt][nt], a[mt], b[nt]);
        }
    }

    const float* bs = reinterpret_cast<const float*>(smem + SM_BIAS);
    const int rq = lane >> 2, c2 = (lane & 3) * 2;
#pragma unroll
    for (int mt = 0; mt < 2; ++mt) {
        const int r0 = row0 + mw + mt * 16 + rq;
#pragma unroll
        for (int nt = 0; nt < 8; ++nt) {
            const int col = nw + nt * 8 + c2;
            const float bx = bs[col], by = bs[col + 1];
            if (r0 < M)
                *reinterpret_cast<float2*>(C + (size_t)r0 * 128 + col) =
                    make_float2(acc[mt][nt][0] + bx, acc[mt][nt][1] + by);
            if (r0 + 8 < M)
                *reinterpret_cast<float2*>(C + (size_t)(r0 + 8) * 128 + col) =
                    make_float2(acc[mt][nt][2] + bx, acc[mt][nt][3] + by);
        }
    }
}

// ---------------------------------------------------------------------------
// CSR build (once; graph shared by both layers)
// ---------------------------------------------------------------------------
__global__ void zero_int_kernel(int* p, int n)
{
    int i = blockIdx.x * blockDim.x + threadIdx.x;
    if (i < n) p[i] = 0;
}

__global__ void deg_kernel(const int* __restrict__ dst, int* __restrict__ deg)
{
    int e = blockIdx.x * blockDim.x + threadIdx.x;
    if (e < NE) atomicAdd(deg + dst[e], 1);
}

// single-block loop scan: rowptr[0]=0, rowptr[i+1]=sum(deg[0..i])
__global__ __launch_bounds__(1024) void scan_kernel(const int* __restrict__ deg,
                                                    int* __restrict__ rowptr,
                                                    int* __restrict__ wpos)
{
    __shared__ int warpsum[32];
    __shared__ int carry_s;
    const int tid = threadIdx.x, lane = tid & 31, wid = tid >> 5;
    if (tid == 0) { carry_s = 0; rowptr[0] = 0; }
    __syncthreads();
    for (int base = 0; base < NN; base += 1024) {
        int i = base + tid;
        int v = (i < NN) ? deg[i] : 0;
        int x = v;
#pragma unroll
        for (int o = 1; o < 32; o <<= 1) {
            int y = __shfl_up_sync(0xffffffffu, x, o);
            if (lane >= o) x += y;
        }
        if (lane == 31) warpsum[wid] = x;
        __syncthreads();
        if (wid == 0) {
            int s = warpsum[lane];
#pragma unroll
            for (int o = 1; o < 32; o <<= 1) {
                int y = __shfl_up_sync(0xffffffffu, s, o);
                if (lane >= o) s += y;
            }
            warpsum[lane] = s;
        }
        __syncthreads();
        int incl = x + (wid > 0 ? warpsum[wid - 1] : 0) + carry_s;
        if (i < NN) { rowptr[i + 1] = incl; wpos[i] = incl - v; }  // wpos = exclusive
        __syncthreads();
        if (tid == 1023) carry_s = incl;
        __syncthreads();
    }
}

__global__ void csr_scatter(const int* __restrict__ src, const int* __restrict__ dst,
                            int* __restrict__ wpos,
                            int* __restrict__ csr_src, int* __restrict__ csr_e)
{
    int e = blockIdx.x * blockDim.x + threadIdx.x;
    if (e >= NE) return;
    int d = __ldg(dst + e);
    int p = atomicAdd(wpos + d, 1);
    csr_src[p] = __ldg(src + e);
    csr_e[p]   = e;
}

// ---------------------------------------------------------------------------
// aggregation: one warp per dst node, register accumulators, no atomics.
//   w_e = exp(<h[d],hW1[s]> + <g[d],ef_e>)
//   wsumh[d] = sum w_e hW1[s];  sbuf[d] = sum w_e ef_e;  denom[d] = sum w_e
// ---------------------------------------------------------------------------
__global__ __launch_bounds__(256) void agg_kernel(
    const float* __restrict__ h, const float* __restrict__ hW1,
    const float* __restrict__ g, const float* __restrict__ ef,
    const int* __restrict__ rowptr, const int* __restrict__ csr_src,
    const int* __restrict__ csr_e,
    float* __restrict__ denom, float* __restrict__ wsumh, float* __restrict__ sbuf)
{
    const int n = blockIdx.x * 8 + (threadIdx.x >> 5);
    if (n >= NN) return;
    const int lane = threadIdx.x & 31;
    const int beg = __ldg(rowptr + n), end = __ldg(rowptr + n + 1);

    float4 ah = make_float4(0.f, 0.f, 0.f, 0.f);
    float4 ae = make_float4(0.f, 0.f, 0.f, 0.f);
    float den = 0.f;

    if (beg < end) {
        const float4 hd = __ldg(reinterpret_cast<const float4*>(h) + n * 32 + lane);
        const float4 gd = __ldg(reinterpret_cast<const float4*>(g) + n * 32 + lane);

        for (int i = beg; i < end; ++i) {
            const int s = __ldg(csr_src + i);
            const int e = __ldg(csr_e + i);
            const float4 hw = __ldg(reinterpret_cast<const float4*>(hW1) + (size_t)s * 32 + lane);
            const float4 ev = __ldg(reinterpret_cast<const float4*>(ef)  + (size_t)e * 32 + lane);

            float p = hd.x * hw.x + hd.y * hw.y + hd.z * hw.z + hd.w * hw.w
                    + gd.x * ev.x + gd.y * ev.y + gd.z * ev.z + gd.w * ev.w;
#pragma unroll
            for (int o = 16; o > 0; o >>= 1) p += __shfl_xor_sync(0xffffffffu, p, o);

            const float w = __expf(p);
            ah.x += w * hw.x; ah.y += w * hw.y; ah.z += w * hw.z; ah.w += w * hw.w;
            ae.x += w * ev.x; ae.y += w * ev.y; ae.z += w * ev.z; ae.w += w * ev.w;
            den += w;
        }
    }

    reinterpret_cast<float4*>(wsumh)[n * 32 + lane] = ah;
    reinterpret_cast<float4*>(sbuf)[n * 32 + lane]  = ae;
    if (lane == 0) denom[n] = den;
}

// ---------------------------------------------------------------------------
// finalize: out = lrelu(selfm + (wsumh + sW1)/max(denom,1e-30))
// deg==0 rows patched afterwards by fixup_iso.
// ---------------------------------------------------------------------------
__global__ __launch_bounds__(256) void finalize_kernel(
    const float* __restrict__ wsumh, const float* __restrict__ sW1,
    const float* __restrict__ denom, const float* __restrict__ selfm,
    float* __restrict__ out)
{
    int i = blockIdx.x * blockDim.x + threadIdx.x;
    if (i >= NN * 32) return;
    int n = i >> 5;

    float4 ws = __ldg(reinterpret_cast<const float4*>(wsumh) + i);
    float4 sv = __ldg(reinterpret_cast<const float4*>(sW1)   + i);
    float inv = 1.0f / fmaxf(__ldg(denom + n), 1e-30f);
    float4 sm = __ldg(reinterpret_cast<const float4*>(selfm) + i);

    float4 r;
    r.x = lrelu(sm.x + (ws.x + sv.x) * inv);
    r.y = lrelu(sm.y + (ws.y + sv.y) * inv);
    r.z = lrelu(sm.z + (ws.z + sv.z) * inv);
    r.w = lrelu(sm.w + (ws.w + sv.w) * inv);
    reinterpret_cast<float4*>(out)[i] = r;
}

// ---------------------------------------------------------------------------
// fixup: for the rare deg==0 nodes, out = lrelu(h@W3 + b3).  warp/node.
// ---------------------------------------------------------------------------
__global__ __launch_bounds__(256) void fixup_iso(
    const float* __restrict__ h, const float* __restrict__ W3,
    const float* __restrict__ b3, const int* __restrict__ rowptr,
    float* __restrict__ out)
{
    int n = blockIdx.x * 8 + (threadIdx.x >> 5);
    if (n >= NN) return;
    if (__ldg(rowptr + n + 1) != __ldg(rowptr + n)) return;
    int lane = threadIdx.x & 31;
    int c0 = lane * 4;

    float acc0 = __ldg(b3 + c0), acc1 = __ldg(b3 + c0 + 1);
    float acc2 = __ldg(b3 + c0 + 2), acc3 = __ldg(b3 + c0 + 3);
    for (int k = 0; k < 128; ++k) {
        float hv = __ldg(h + (size_t)n * 128 + k);
        const float* wr = W3 + (size_t)k * 128 + c0;
        acc0 += hv * __ldg(wr);
        acc1 += hv * __ldg(wr + 1);
        acc2 += hv * __ldg(wr + 2);
        acc3 += hv * __ldg(wr + 3);
    }
    float4 r = make_float4(lrelu(acc0), lrelu(acc1), lrelu(acc2), lrelu(acc3));
    *reinterpret_cast<float4*>(out + (size_t)n * 128 + c0) = r;
}

// ---------------------------------------------------------------------------
// launch
// ---------------------------------------------------------------------------
extern "C" void kernel_launch(void* const* d_in, const int* in_sizes, int n_in,
                              void* d_out, int out_size)
{
    const float* node = (const float*)d_in[0];
    const float* ef   = (const float*)d_in[1];
    const int*   src  = (const int*)d_in[2];
    const int*   dst  = (const int*)d_in[3];
    const float* W1[2] = {(const float*)d_in[4],  (const float*)d_in[10]};
    const float* B1[2] = {(const float*)d_in[5],  (const float*)d_in[11]};
    const float* W2[2] = {(const float*)d_in[6],  (const float*)d_in[12]};
    const float* B2[2] = {(const float*)d_in[7],  (const float*)d_in[13]};
    const float* W3[2] = {(const float*)d_in[8],  (const float*)d_in[14]};
    const float* B3[2] = {(const float*)d_in[9],  (const float*)d_in[15]};

    float* base = nullptr;
    cudaGetSymbolAddress((void**)&base, g_scratch);

    float* hW1    = base + O_HW1;
    float* g      = base + O_G;
    float* selfm  = base + O_SELF;
    float* wsumh  = base + O_WSUM;
    float* sbuf   = base + O_S;
    float* sW1    = base + O_SW1;
    float* h1     = base + O_H1;
    float* denom  = base + O_DEN;
    int*   deg    = (int*)(base + O_DEG);
    int*   rowptr = (int*)(base + O_ROWPTR);
    int*   wpos   = (int*)(base + O_WPOS);
    int*   csrs   = (int*)(base + O_CSRS);
    int*   csre   = (int*)(base + O_CSRE);

    cudaFuncSetAttribute(tc_gemm<1>, cudaFuncAttributeMaxDynamicSharedMemorySize, GEMM_SMEM);
    cudaFuncSetAttribute(tc_gemm<0>, cudaFuncAttributeMaxDynamicSharedMemorySize, GEMM_SMEM);

    // ---- CSR build (once) ----
    zero_int_kernel<<<(NN + 255) / 256, 256>>>(deg, NN);
    deg_kernel<<<(NE + 255) / 256, 256>>>(dst, deg);
    scan_kernel<<<1, 1024>>>(deg, rowptr, wpos);
    csr_scatter<<<(NE + 255) / 256, 256>>>(src, dst, wpos, csrs, csre);

    const int gemmGrid = (NN + 127) / 128;   // 391
    const int nodeGrid = (NN + 7) / 8;       // 6250

    const float* h = node;
    float* out_l[2] = {h1, (float*)d_out};

    for (int l = 0; l < 2; ++l) {
        tc_gemm<1><<<gemmGrid, 256, GEMM_SMEM>>>(h, W1[l], B1[l], hW1,   NN);
        tc_gemm<0><<<gemmGrid, 256, GEMM_SMEM>>>(h, W1[l], nullptr, g,   NN);  // h @ W1^T
        tc_gemm<1><<<gemmGrid, 256, GEMM_SMEM>>>(h, W2[l], B2[l], selfm, NN);

        agg_kernel<<<nodeGrid, 256>>>(h, hW1, g, ef, rowptr, csrs, csre,
                                      denom, wsumh, sbuf);

        tc_gemm<1><<<gemmGrid, 256, GEMM_SMEM>>>(sbuf, W1[l], nullptr, sW1, NN);

        finalize_kernel<<<(NN * 32 + 255) / 256, 256>>>(wsumh, sW1, denom, selfm, out_l[l]);
        fixup_iso<<<nodeGrid, 256>>>(h, W3[l], B3[l], rowptr, out_l[l]);

        h = h1;
    }
}

// round 9
// speedup vs baseline: 1.6732x; 1.0552x over previous
#include <cuda_runtime.h>
#include <cuda_bf16.h>
#include <cstdint>

// ---------------------------------------------------------------------------
// RelGAT restructured:
//   score_e = <h[dst], hW1[src]> + <g[dst], efeat_e>,  g = h@W1^T, hW1 = h@W1+b1
//   neigh_d = ( sum w_e hW1[src] + (sum w_e efeat_e)@W1 ) / denom
// Round 9:
//  - 3 A-sharing GEMMs batched via gridDim.y (independent CTAs overlap phases)
//  - finalize fused into the sW1 GEMM epilogue (FIN) -> no sW1 round-trip
//  - agg_kernel ILP-2 software pipelining across the shfl reduction chain
// ---------------------------------------------------------------------------

namespace {
constexpr int    NN  = 50000;
constexpr int    NE  = 600000;
constexpr size_t ND  = (size_t)NN * 128;
constexpr float  NEG_SLOPE = 0.22916666666666666f;

constexpr size_t O_HW1  = 0;
constexpr size_t O_G    = 1 * ND;
constexpr size_t O_SELF = 2 * ND;
constexpr size_t O_WSUM = 3 * ND;
constexpr size_t O_S    = 4 * ND;
constexpr size_t O_H1   = 5 * ND;
constexpr size_t O_DEN    = 6 * ND;            // NN floats
constexpr size_t O_DEG    = O_DEN + NN;        // NN ints
constexpr size_t O_ROWPTR = O_DEG + NN;        // NN+1 ints
constexpr size_t O_WPOS   = O_ROWPTR + NN + 1; // NN ints
constexpr size_t O_CSRS   = O_WPOS + NN;       // NE ints
constexpr size_t O_CSRE   = O_CSRS + NE;       // NE ints
constexpr size_t SCRATCH  = O_CSRE + NE;

// GEMM smem layout (bytes); padded rows: 128 bf16 + 8 pad = 272 B/row.
constexpr int LDTB       = 272;
constexpr int TILE_BYTES = 128 * LDTB;     // 34816
constexpr int SM_BIAS = 0;
constexpr int SA_HI = 512;
constexpr int SA_LO = SA_HI + TILE_BYTES;
constexpr int SB_HI = SA_LO + TILE_BYTES;
constexpr int SB_LO = SB_HI + TILE_BYTES;
constexpr int GEMM_SMEM = SB_LO + TILE_BYTES;   // 139,776 B
}  // namespace

__device__ float g_scratch[SCRATCH];

// ---------------------------------------------------------------------------
// warp-MMA helpers
// ---------------------------------------------------------------------------
__device__ __forceinline__ uint32_t smem_u32(const void* p) {
    uint32_t a;
    asm("{ .reg .u64 t; cvta.to.shared.u64 t, %1; cvt.u32.u64 %0, t; }" : "=r"(a) : "l"(p));
    return a;
}
__device__ __forceinline__ void ldsm_x4(uint32_t* r, uint32_t addr) {
    asm volatile("ldmatrix.sync.aligned.m8n8.x4.shared.b16 {%0,%1,%2,%3}, [%4];"
                 : "=r"(r[0]), "=r"(r[1]), "=r"(r[2]), "=r"(r[3]) : "r"(addr));
}
__device__ __forceinline__ void ldsm_x2t(uint32_t* r, uint32_t addr) {
    asm volatile("ldmatrix.sync.aligned.m8n8.x2.trans.shared.b16 {%0,%1}, [%2];"
                 : "=r"(r[0]), "=r"(r[1]) : "r"(addr));
}
__device__ __forceinline__ void ldsm_x2(uint32_t* r, uint32_t addr) {
    asm volatile("ldmatrix.sync.aligned.m8n8.x2.shared.b16 {%0,%1}, [%2];"
                 : "=r"(r[0]), "=r"(r[1]) : "r"(addr));
}
__device__ __forceinline__ void mma_bf16(float* d, const uint32_t* a, const uint32_t* b) {
    asm volatile("mma.sync.aligned.m16n8k16.row.col.f32.bf16.bf16.f32 "
                 "{%0,%1,%2,%3}, {%4,%5,%6,%7}, {%8,%9}, {%0,%1,%2,%3};"
                 : "+f"(d[0]), "+f"(d[1]), "+f"(d[2]), "+f"(d[3])
                 : "r"(a[0]), "r"(a[1]), "r"(a[2]), "r"(a[3]), "r"(b[0]), "r"(b[1]));
}
__device__ __forceinline__ void split_store(char* hiB, char* loB, uint32_t off, float4 v) {
    __nv_bfloat162 h01 = __float22bfloat162_rn(make_float2(v.x, v.y));
    __nv_bfloat162 h23 = __float22bfloat162_rn(make_float2(v.z, v.w));
    float2 f01 = __bfloat1622float2(h01);
    float2 f23 = __bfloat1622float2(h23);
    __nv_bfloat162 l01 = __float22bfloat162_rn(make_float2(v.x - f01.x, v.y - f01.y));
    __nv_bfloat162 l23 = __float22bfloat162_rn(make_float2(v.z - f23.x, v.w - f23.y));
    *reinterpret_cast<__nv_bfloat162*>(hiB + off)     = h01;
    *reinterpret_cast<__nv_bfloat162*>(hiB + off + 4) = h23;
    *reinterpret_cast<__nv_bfloat162*>(loB + off)     = l01;
    *reinterpret_cast<__nv_bfloat162*>(loB + off + 4) = l23;
}
__device__ __forceinline__ float lrelu(float v) { return v >= 0.f ? v : v * NEG_SLOPE; }

// ---------------------------------------------------------------------------
// GEMM body (R5 structure).  One (A-tile, weight) pair per CTA.
// wkn=1: W stored [k][n] (C=A@W, trans ldmatrix).  wkn=0: C=A@W^T, non-trans.
// FIN: epilogue computes out = lrelu(selfm + (wsumh + acc)/max(denom,1e-30)).
// ---------------------------------------------------------------------------
template <bool FIN>
__device__ __forceinline__ void gemm_body(
    const float* __restrict__ A, const float* __restrict__ W,
    const float* __restrict__ bias, float* __restrict__ C, int wkn, int M,
    const float* __restrict__ wsumh, const float* __restrict__ denom,
    const float* __restrict__ selfm, char* smem)
{
    const uint32_t sb = smem_u32(smem);
    const int tid = threadIdx.x, wid = tid >> 5, lane = tid & 31;
    const int row0 = blockIdx.x * 128;

    if (!FIN && tid < 128)
        reinterpret_cast<float*>(smem + SM_BIAS)[tid] = bias ? bias[tid] : 0.f;

    {
        const int r = tid >> 1, ch = (tid & 1) << 6;
        const bool valid = (row0 + r) < M;
        const float4* ap = reinterpret_cast<const float4*>(A + (size_t)(row0 + r) * 128 + ch);
#pragma unroll
        for (int i = 0; i < 16; ++i) {
            float4 v = valid ? __ldg(ap + i) : make_float4(0.f, 0.f, 0.f, 0.f);
            split_store(smem + SA_HI, smem + SA_LO, r * LDTB + (ch + i * 4) * 2, v);
        }
    }
    {
        const int r = tid >> 1, ch = (tid & 1) << 6;
        const float4* wp = reinterpret_cast<const float4*>(W + (size_t)r * 128 + ch);
#pragma unroll
        for (int i = 0; i < 16; ++i) {
            float4 v = __ldg(wp + i);
            split_store(smem + SB_HI, smem + SB_LO, r * LDTB + (ch + i * 4) * 2, v);
        }
    }
    __syncthreads();

    const int mw = (wid & 3) * 32;
    const int nw = (wid >> 2) * 64;

    float acc[2][8][4];
#pragma unroll
    for (int mt = 0; mt < 2; ++mt)
#pragma unroll
        for (int nt = 0; nt < 8; ++nt)
#pragma unroll
            for (int j = 0; j < 4; ++j) acc[mt][nt][j] = 0.f;

    const uint32_t a_row_off = (mw + (lane & 15)) * LDTB + ((lane >> 4) << 3) * 2;
    const uint32_t bt_row    = (lane & 15) * LDTB;
    const uint32_t bn_off    = (lane & 7) * LDTB + (((lane >> 3) & 1) << 3) * 2;

#pragma unroll
    for (int g = 0; g < 3; ++g) {
        const uint32_t abase = sb + (g == 2 ? SA_LO : SA_HI);
        const uint32_t bbase = sb + (g == 1 ? SB_LO : SB_HI);
#pragma unroll
        for (int kk = 0; kk < 8; ++kk) {
            uint32_t a[2][4];
            ldsm_x4(a[0], abase + a_row_off + kk * 32);
            ldsm_x4(a[1], abase + a_row_off + 16 * LDTB + kk * 32);
            uint32_t b[8][2];
#pragma unroll
            for (int nt = 0; nt < 8; ++nt) {
                if (wkn)
                    ldsm_x2t(b[nt], bbase + kk * 16 * LDTB + bt_row + (nw + nt * 8) * 2);
                else
                    ldsm_x2(b[nt], bbase + (nw + nt * 8) * LDTB + bn_off + kk * 32);
            }
#pragma unroll
            for (int mt = 0; mt < 2; ++mt)
#pragma unroll
                for (int nt = 0; nt < 8; ++nt)
                    mma_bf16(acc[mt][nt], a[mt], b[nt]);
        }
    }

    const int rq = lane >> 2, c2 = (lane & 3) * 2;
    if (!FIN) {
        const float* bs = reinterpret_cast<const float*>(smem + SM_BIAS);
#pragma unroll
        for (int mt = 0; mt < 2; ++mt) {
            const int r0 = row0 + mw + mt * 16 + rq;
#pragma unroll
            for (int nt = 0; nt < 8; ++nt) {
                const int col = nw + nt * 8 + c2;
                const float bx = bs[col], by = bs[col + 1];
                if (r0 < M)
                    *reinterpret_cast<float2*>(C + (size_t)r0 * 128 + col) =
                        make_float2(acc[mt][nt][0] + bx, acc[mt][nt][1] + by);
                if (r0 + 8 < M)
                    *reinterpret_cast<float2*>(C + (size_t)(r0 + 8) * 128 + col) =
                        make_float2(acc[mt][nt][2] + bx, acc[mt][nt][3] + by);
            }
        }
    } else {
#pragma unroll
        for (int mt = 0; mt < 2; ++mt) {
            const int rA = row0 + mw + mt * 16 + rq;
            const int rB = rA + 8;
            float invA = 0.f, invB = 0.f;
            if (rA < M) invA = 1.0f / fmaxf(__ldg(denom + rA), 1e-30f);
            if (rB < M) invB = 1.0f / fmaxf(__ldg(denom + rB), 1e-30f);
#pragma unroll
            for (int nt = 0; nt < 8; ++nt) {
                const int col = nw + nt * 8 + c2;
                if (rA < M) {
                    float2 ws = __ldg(reinterpret_cast<const float2*>(wsumh + (size_t)rA * 128 + col));
                    float2 sm = __ldg(reinterpret_cast<const float2*>(selfm + (size_t)rA * 128 + col));
                    *reinterpret_cast<float2*>(C + (size_t)rA * 128 + col) = make_float2(
                        lrelu(sm.x + (ws.x + acc[mt][nt][0]) * invA),
                        lrelu(sm.y + (ws.y + acc[mt][nt][1]) * invA));
                }
                if (rB < M) {
                    float2 ws = __ldg(reinterpret_cast<const float2*>(wsumh + (size_t)rB * 128 + col));
                    float2 sm = __ldg(reinterpret_cast<const float2*>(selfm + (size_t)rB * 128 + col));
                    *reinterpret_cast<float2*>(C + (size_t)rB * 128 + col) = make_float2(
                        lrelu(sm.x + (ws.x + acc[mt][nt][2]) * invB),
                        lrelu(sm.y + (ws.y + acc[mt][nt][3]) * invB));
                }
            }
        }
    }
}

// batched GEMM: gridDim.y selects (W, bias, C, wkn) slot; all share A.
__global__ __launch_bounds__(256, 1)
void tc_gemm3(const float* __restrict__ A,
              const float* __restrict__ W0, const float* __restrict__ W1,
              const float* __restrict__ W2,
              const float* __restrict__ b0, const float* __restrict__ b1,
              const float* __restrict__ b2,
              float* __restrict__ C0, float* __restrict__ C1, float* __restrict__ C2,
              int wknMask, int M)
{
    extern __shared__ char smem[];
    const int y = blockIdx.y;
    const float* W = (y == 0) ? W0 : (y == 1) ? W1 : W2;
    const float* b = (y == 0) ? b0 : (y == 1) ? b1 : b2;
    float*       C = (y == 0) ? C0 : (y == 1) ? C1 : C2;
    gemm_body<false>(A, W, b, C, (wknMask >> y) & 1, M,
                     nullptr, nullptr, nullptr, smem);
}

// single GEMM with fused finalize epilogue
__global__ __launch_bounds__(256, 1)
void tc_gemm_fin(const float* __restrict__ A, const float* __restrict__ W,
                 float* __restrict__ out,
                 const float* __restrict__ wsumh, const float* __restrict__ denom,
                 const float* __restrict__ selfm, int M)
{
    extern __shared__ char smem[];
    gemm_body<true>(A, W, nullptr, out, 1, M, wsumh, denom, selfm, smem);
}

// ---------------------------------------------------------------------------
// CSR build (once; graph shared by both layers)
// ---------------------------------------------------------------------------
__global__ void zero_int_kernel(int* p, int n)
{
    int i = blockIdx.x * blockDim.x + threadIdx.x;
    if (i < n) p[i] = 0;
}

__global__ void deg_kernel(const int* __restrict__ dst, int* __restrict__ deg)
{
    int e = blockIdx.x * blockDim.x + threadIdx.x;
    if (e < NE) atomicAdd(deg + dst[e], 1);
}

__global__ __launch_bounds__(1024) void scan_kernel(const int* __restrict__ deg,
                                                    int* __restrict__ rowptr,
                                                    int* __restrict__ wpos)
{
    __shared__ int warpsum[32];
    __shared__ int carry_s;
    const int tid = threadIdx.x, lane = tid & 31, wid = tid >> 5;
    if (tid == 0) { carry_s = 0; rowptr[0] = 0; }
    __syncthreads();
    for (int base = 0; base < NN; base += 1024) {
        int i = base + tid;
        int v = (i < NN) ? deg[i] : 0;
        int x = v;
#pragma unroll
        for (int o = 1; o < 32; o <<= 1) {
            int y = __shfl_up_sync(0xffffffffu, x, o);
            if (lane >= o) x += y;
        }
        if (lane == 31) warpsum[wid] = x;
        __syncthreads();
        if (wid == 0) {
            int s = warpsum[lane];
#pragma unroll
            for (int o = 1; o < 32; o <<= 1) {
                int y = __shfl_up_sync(0xffffffffu, s, o);
                if (lane >= o) s += y;
            }
            warpsum[lane] = s;
        }
        __syncthreads();
        int incl = x + (wid > 0 ? warpsum[wid - 1] : 0) + carry_s;
        if (i < NN) { rowptr[i + 1] = incl; wpos[i] = incl - v; }
        __syncthreads();
        if (tid == 1023) carry_s = incl;
        __syncthreads();
    }
}

__global__ void csr_scatter(const int* __restrict__ src, const int* __restrict__ dst,
                            int* __restrict__ wpos,
                            int* __restrict__ csr_src, int* __restrict__ csr_e)
{
    int e = blockIdx.x * blockDim.x + threadIdx.x;
    if (e >= NE) return;
    int d = __ldg(dst + e);
    int p = atomicAdd(wpos + d, 1);
    csr_src[p] = __ldg(src + e);
    csr_e[p]   = e;
}

// ---------------------------------------------------------------------------
// aggregation: one warp per dst node, register accumulators, ILP-2 pipeline.
// ---------------------------------------------------------------------------
__global__ __launch_bounds__(256) void agg_kernel(
    const float* __restrict__ h, const float* __restrict__ hW1,
    const float* __restrict__ g, const float* __restrict__ ef,
    const int* __restrict__ rowptr, const int* __restrict__ csr_src,
    const int* __restrict__ csr_e,
    float* __restrict__ denom, float* __restrict__ wsumh, float* __restrict__ sbuf)
{
    const int n = blockIdx.x * 8 + (threadIdx.x >> 5);
    if (n >= NN) return;
    const int lane = threadIdx.x & 31;
    const int beg = __ldg(rowptr + n), end = __ldg(rowptr + n + 1);

    float4 ah = make_float4(0.f, 0.f, 0.f, 0.f);
    float4 ae = make_float4(0.f, 0.f, 0.f, 0.f);
    float den = 0.f;

    if (beg < end) {
        const float4 hd = __ldg(reinterpret_cast<const float4*>(h) + n * 32 + lane);
        const float4 gd = __ldg(reinterpret_cast<const float4*>(g) + n * 32 + lane);

        // prologue: load edge[beg]
        int s = __ldg(csr_src + beg);
        int e = __ldg(csr_e + beg);
        float4 hw = __ldg(reinterpret_cast<const float4*>(hW1) + (size_t)s * 32 + lane);
        float4 ev = __ldg(reinterpret_cast<const float4*>(ef)  + (size_t)e * 32 + lane);

        for (int i = beg; ; ) {
            // prefetch next edge before the dependent reduction chain
            const int i2 = i + 1;
            const bool more = i2 < end;
            int s2 = 0, e2 = 0;
            float4 hw2, ev2;
            if (more) {
                s2 = __ldg(csr_src + i2);
                e2 = __ldg(csr_e + i2);
                hw2 = __ldg(reinterpret_cast<const float4*>(hW1) + (size_t)s2 * 32 + lane);
                ev2 = __ldg(reinterpret_cast<const float4*>(ef)  + (size_t)e2 * 32 + lane);
            }

            float p = hd.x * hw.x + hd.y * hw.y + hd.z * hw.z + hd.w * hw.w
                    + gd.x * ev.x + gd.y * ev.y + gd.z * ev.z + gd.w * ev.w;
#pragma unroll
            for (int o = 16; o > 0; o >>= 1) p += __shfl_xor_sync(0xffffffffu, p, o);

            const float w = __expf(p);
            ah.x += w * hw.x; ah.y += w * hw.y; ah.z += w * hw.z; ah.w += w * hw.w;
            ae.x += w * ev.x; ae.y += w * ev.y; ae.z += w * ev.z; ae.w += w * ev.w;
            den += w;

            if (!more) break;
            i = i2; hw = hw2; ev = ev2;
        }
    }

    reinterpret_cast<float4*>(wsumh)[n * 32 + lane] = ah;
    reinterpret_cast<float4*>(sbuf)[n * 32 + lane]  = ae;
    if (lane == 0) denom[n] = den;
}

// ---------------------------------------------------------------------------
// fixup: for the rare deg==0 nodes, out = lrelu(h@W3 + b3).  warp/node.
// ---------------------------------------------------------------------------
__global__ __launch_bounds__(256) void fixup_iso(
    const float* __restrict__ h, const float* __restrict__ W3,
    const float* __restrict__ b3, const int* __restrict__ rowptr,
    float* __restrict__ out)
{
    int n = blockIdx.x * 8 + (threadIdx.x >> 5);
    if (n >= NN) return;
    if (__ldg(rowptr + n + 1) != __ldg(rowptr + n)) return;
    int lane = threadIdx.x & 31;
    int c0 = lane * 4;

    float acc0 = __ldg(b3 + c0), acc1 = __ldg(b3 + c0 + 1);
    float acc2 = __ldg(b3 + c0 + 2), acc3 = __ldg(b3 + c0 + 3);
    for (int k = 0; k < 128; ++k) {
        float hv = __ldg(h + (size_t)n * 128 + k);
        const float* wr = W3 + (size_t)k * 128 + c0;
        acc0 += hv * __ldg(wr);
        acc1 += hv * __ldg(wr + 1);
        acc2 += hv * __ldg(wr + 2);
        acc3 += hv * __ldg(wr + 3);
    }
    float4 r = make_float4(lrelu(acc0), lrelu(acc1), lrelu(acc2), lrelu(acc3));
    *reinterpret_cast<float4*>(out + (size_t)n * 128 + c0) = r;
}

// ---------------------------------------------------------------------------
// launch
// ---------------------------------------------------------------------------
extern "C" void kernel_launch(void* const* d_in, const int* in_sizes, int n_in,
                              void* d_out, int out_size)
{
    const float* node = (const float*)d_in[0];
    const float* ef   = (const float*)d_in[1];
    const int*   src  = (const int*)d_in[2];
    const int*   dst  = (const int*)d_in[3];
    const float* W1[2] = {(const float*)d_in[4],  (const float*)d_in[10]};
    const float* B1[2] = {(const float*)d_in[5],  (const float*)d_in[11]};
    const float* W2[2] = {(const float*)d_in[6],  (const float*)d_in[12]};
    const float* B2[2] = {(const float*)d_in[7],  (const float*)d_in[13]};
    const float* W3[2] = {(const float*)d_in[8],  (const float*)d_in[14]};
    const float* B3[2] = {(const float*)d_in[9],  (const float*)d_in[15]};

    float* base = nullptr;
    cudaGetSymbolAddress((void**)&base, g_scratch);

    float* hW1    = base + O_HW1;
    float* g      = base + O_G;
    float* selfm  = base + O_SELF;
    float* wsumh  = base + O_WSUM;
    float* sbuf   = base + O_S;
    float* h1     = base + O_H1;
    float* denom  = base + O_DEN;
    int*   deg    = (int*)(base + O_DEG);
    int*   rowptr = (int*)(base + O_ROWPTR);
    int*   wpos   = (int*)(base + O_WPOS);
    int*   csrs   = (int*)(base + O_CSRS);
    int*   csre   = (int*)(base + O_CSRE);

    cudaFuncSetAttribute(tc_gemm3,    cudaFuncAttributeMaxDynamicSharedMemorySize, GEMM_SMEM);
    cudaFuncSetAttribute(tc_gemm_fin, cudaFuncAttributeMaxDynamicSharedMemorySize, GEMM_SMEM);

    // ---- CSR build (once) ----
    zero_int_kernel<<<(NN + 255) / 256, 256>>>(deg, NN);
    deg_kernel<<<(NE + 255) / 256, 256>>>(dst, deg);
    scan_kernel<<<1, 1024>>>(deg, rowptr, wpos);
    csr_scatter<<<(NE + 255) / 256, 256>>>(src, dst, wpos, csrs, csre);

    const int gemmGrid = (NN + 127) / 128;   // 391
    const int nodeGrid = (NN + 7) / 8;       // 6250

    const float* h = node;
    float* out_l[2] = {h1, (float*)d_out};

    for (int l = 0; l < 2; ++l) {
        // y=0: hW1 = h@W1+b1 (wkn1);  y=1: g = h@W1^T (wkn0);  y=2: selfm (wkn1)
        tc_gemm3<<<dim3(gemmGrid, 3), 256, GEMM_SMEM>>>(
            h, W1[l], W1[l], W2[l], B1[l], nullptr, B2[l],
            hW1, g, selfm, 0b101, NN);

        agg_kernel<<<nodeGrid, 256>>>(h, hW1, g, ef, rowptr, csrs, csre,
                                      denom, wsumh, sbuf);

        // out = lrelu(selfm + (wsumh + sbuf@W1)/denom)
        tc_gemm_fin<<<gemmGrid, 256, GEMM_SMEM>>>(sbuf, W1[l], out_l[l],
                                                  wsumh, denom, selfm, NN);

        fixup_iso<<<nodeGrid, 256>>>(h, W3[l], B3[l], rowptr, out_l[l]);

        h = h1;
    }
}

// round 10
// speedup vs baseline: 1.7828x; 1.0655x over previous
#include <cuda_runtime.h>
#include <cuda_bf16.h>
#include <cstdint>

// ---------------------------------------------------------------------------
// RelGAT restructured:
//   score_e = <h[dst], hW1[src]> + <g[dst], efeat_e>,  g = h@W1^T, hW1 = h@W1+b1
//   neigh_d = ( sum w_e hW1[src] + (sum w_e efeat_e)@W1 ) / denom
// Round 10:
//  - GEMM K-chunked (2 x K=64), 72KB smem -> 2 CTAs/SM (R6 chunk addressing,
//    verified correct; single weight per CTA so A is loaded exactly once)
//  - agg: two interleaved per-edge reduction chains (halve exposed shfl depth)
//  - keeps: gridDim.y=3 batched A-sharing GEMMs, fused finalize epilogue,
//    dst-CSR aggregation, softmax rescale, iso fixup.
// ---------------------------------------------------------------------------

namespace {
constexpr int    NN  = 50000;
constexpr int    NE  = 600000;
constexpr size_t ND  = (size_t)NN * 128;
constexpr float  NEG_SLOPE = 0.22916666666666666f;

constexpr size_t O_HW1  = 0;
constexpr size_t O_G    = 1 * ND;
constexpr size_t O_SELF = 2 * ND;
constexpr size_t O_WSUM = 3 * ND;
constexpr size_t O_S    = 4 * ND;
constexpr size_t O_H1   = 5 * ND;
constexpr size_t O_DEN    = 6 * ND;            // NN floats
constexpr size_t O_DEG    = O_DEN + NN;        // NN ints
constexpr size_t O_ROWPTR = O_DEG + NN;        // NN+1 ints
constexpr size_t O_WPOS   = O_ROWPTR + NN + 1; // NN ints
constexpr size_t O_CSRS   = O_WPOS + NN;       // NE ints
constexpr size_t O_CSRE   = O_CSRS + NE;       // NE ints
constexpr size_t SCRATCH  = O_CSRE + NE;

// K-chunked GEMM smem (bytes), chunk K=64:
// A tile: 128 rows x (64 bf16 + 8 pad) = 144 B/row
// B trans ([k][n]): 64 rows x (128 bf16 + 8 pad) = 272 B/row (17408 B)
// B non-trans ([n][k]): 128 rows x 144 B (18432 B)
constexpr int LDA  = 144;
constexpr int LDBT = 272;
constexpr int LDBN = 144;
constexpr int A_HI = 0;
constexpr int A_LO = A_HI + 128 * LDA;       // 18432
constexpr int B_HI = A_LO + 128 * LDA;       // 36864
constexpr int B_LO = B_HI + 128 * LDBN;      // 55296
constexpr int GEMM_SMEM = B_LO + 128 * LDBN; // 73728 -> 2 CTAs/SM
}  // namespace

__device__ float g_scratch[SCRATCH];

// ---------------------------------------------------------------------------
// warp-MMA helpers
// ---------------------------------------------------------------------------
__device__ __forceinline__ uint32_t smem_u32(const void* p) {
    uint32_t a;
    asm("{ .reg .u64 t; cvta.to.shared.u64 t, %1; cvt.u32.u64 %0, t; }" : "=r"(a) : "l"(p));
    return a;
}
__device__ __forceinline__ void ldsm_x4(uint32_t* r, uint32_t addr) {
    asm volatile("ldmatrix.sync.aligned.m8n8.x4.shared.b16 {%0,%1,%2,%3}, [%4];"
                 : "=r"(r[0]), "=r"(r[1]), "=r"(r[2]), "=r"(r[3]) : "r"(addr));
}
__device__ __forceinline__ void ldsm_x4t(uint32_t* r, uint32_t addr) {
    asm volatile("ldmatrix.sync.aligned.m8n8.x4.trans.shared.b16 {%0,%1,%2,%3}, [%4];"
                 : "=r"(r[0]), "=r"(r[1]), "=r"(r[2]), "=r"(r[3]) : "r"(addr));
}
__device__ __forceinline__ void mma_bf16(float* d, const uint32_t* a, const uint32_t* b) {
    asm volatile("mma.sync.aligned.m16n8k16.row.col.f32.bf16.bf16.f32 "
                 "{%0,%1,%2,%3}, {%4,%5,%6,%7}, {%8,%9}, {%0,%1,%2,%3};"
                 : "+f"(d[0]), "+f"(d[1]), "+f"(d[2]), "+f"(d[3])
                 : "r"(a[0]), "r"(a[1]), "r"(a[2]), "r"(a[3]), "r"(b[0]), "r"(b[1]));
}
__device__ __forceinline__ void split_store(char* hiB, char* loB, uint32_t off, float4 v) {
    __nv_bfloat162 h01 = __float22bfloat162_rn(make_float2(v.x, v.y));
    __nv_bfloat162 h23 = __float22bfloat162_rn(make_float2(v.z, v.w));
    float2 f01 = __bfloat1622float2(h01);
    float2 f23 = __bfloat1622float2(h23);
    __nv_bfloat162 l01 = __float22bfloat162_rn(make_float2(v.x - f01.x, v.y - f01.y));
    __nv_bfloat162 l23 = __float22bfloat162_rn(make_float2(v.z - f23.x, v.w - f23.y));
    *reinterpret_cast<__nv_bfloat162*>(hiB + off)     = h01;
    *reinterpret_cast<__nv_bfloat162*>(hiB + off + 4) = h23;
    *reinterpret_cast<__nv_bfloat162*>(loB + off)     = l01;
    *reinterpret_cast<__nv_bfloat162*>(loB + off + 4) = l23;
}
__device__ __forceinline__ float lrelu(float v) { return v >= 0.f ? v : v * NEG_SLOPE; }

// ---------------------------------------------------------------------------
// K-chunked GEMM body (R6 addressing, verified): C[M,128] = A@Wmath (+bias)
// wkn=1: W stored [k][n] (C=A@W).  wkn=0: W stored [n][k] (C=A@W^T).
// FIN: epilogue out = lrelu(selfm + (wsumh + acc)/max(denom,1e-30)).
// ---------------------------------------------------------------------------
template <bool FIN>
__device__ __forceinline__ void gemm_body(
    const float* __restrict__ A, const float* __restrict__ W,
    const float* __restrict__ bias, float* __restrict__ C, int wkn, int M,
    const float* __restrict__ wsumh, const float* __restrict__ denom,
    const float* __restrict__ selfm, char* smem)
{
    const uint32_t sb = smem_u32(smem);
    const int tid = threadIdx.x, wid = tid >> 5, lane = tid & 31;
    const int row0 = blockIdx.x * 128;
    const int mw = (wid & 3) * 32, nw = (wid >> 2) * 64;

    const int ar = tid >> 1, acb = (tid & 1) * 32;
    const bool avalid = (row0 + ar) < M;

    const uint32_t a_off  = (uint32_t)((mw + (lane & 15)) * LDA + ((lane >> 4) << 4));
    const uint32_t bt_off = (uint32_t)((((lane >> 3) & 1) * 8 + (lane & 7)) * LDBT
                                       + (nw + ((lane >> 4) << 3)) * 2);
    const uint32_t bn_off = (uint32_t)((nw + ((lane >> 4) << 3) + (lane & 7)) * LDBN
                                       + ((lane >> 3) & 1) * 16);

    float acc[2][8][4];
#pragma unroll
    for (int mt = 0; mt < 2; ++mt)
#pragma unroll
        for (int nt = 0; nt < 8; ++nt)
#pragma unroll
            for (int j = 0; j < 4; ++j) acc[mt][nt][j] = 0.f;

#pragma unroll
    for (int c = 0; c < 2; ++c) {
        __syncthreads();   // protect smem reuse from previous chunk's mma

        // --- A chunk: cols [c*64, c*64+64) ---
        {
            const float4* ap = reinterpret_cast<const float4*>(
                A + (size_t)(row0 + ar) * 128 + c * 64 + acb);
#pragma unroll
            for (int i = 0; i < 8; ++i) {
                float4 v = avalid ? __ldg(ap + i) : make_float4(0.f, 0.f, 0.f, 0.f);
                split_store(smem + A_HI, smem + A_LO, ar * LDA + (acb + i * 4) * 2, v);
            }
        }
        // --- B chunk ---
        if (wkn) {       // [k][n]: 64 k-rows of this chunk
            const int kr = tid >> 2, nb = (tid & 3) * 32;
            const float4* wp = reinterpret_cast<const float4*>(
                W + (size_t)(c * 64 + kr) * 128 + nb);
#pragma unroll
            for (int i = 0; i < 8; ++i) {
                float4 v = __ldg(wp + i);
                split_store(smem + B_HI, smem + B_LO, kr * LDBT + (nb + i * 4) * 2, v);
            }
        } else {         // [n][k]: 128 n-rows, cols = chunk k
            const int nr = tid >> 1, kb = (tid & 1) * 32;
            const float4* wp = reinterpret_cast<const float4*>(
                W + (size_t)nr * 128 + c * 64 + kb);
#pragma unroll
            for (int i = 0; i < 8; ++i) {
                float4 v = __ldg(wp + i);
                split_store(smem + B_HI, smem + B_LO, nr * LDBN + (kb + i * 4) * 2, v);
            }
        }
        __syncthreads();

        // --- MMA: 3 groups (hh, hl, lh) x 4 k16-steps ---
#pragma unroll
        for (int g = 0; g < 3; ++g) {
            const uint32_t abase = sb + (g == 2 ? A_LO : A_HI);
            const uint32_t bbase = sb + (g == 1 ? B_LO : B_HI);
#pragma unroll
            for (int kk = 0; kk < 4; ++kk) {
                uint32_t a0[4], a1[4];
                ldsm_x4(a0, abase + a_off + kk * 32);
                ldsm_x4(a1, abase + a_off + 16 * LDA + kk * 32);
#pragma unroll
                for (int p = 0; p < 4; ++p) {
                    uint32_t b4[4];
                    if (wkn)
                        ldsm_x4t(b4, bbase + bt_off + (uint32_t)(kk * 16 * LDBT + p * 32));
                    else
                        ldsm_x4(b4, bbase + bn_off + (uint32_t)(p * 16 * LDBN + kk * 32));
                    mma_bf16(acc[0][2 * p],     a0, b4);
                    mma_bf16(acc[0][2 * p + 1], a0, b4 + 2);
                    mma_bf16(acc[1][2 * p],     a1, b4);
                    mma_bf16(acc[1][2 * p + 1], a1, b4 + 2);
                }
            }
        }
    }

    // --- epilogue ---
    const int rq = lane >> 2, c2 = (lane & 3) * 2;
    if (!FIN) {
#pragma unroll
        for (int mt = 0; mt < 2; ++mt) {
            const int r0 = row0 + mw + mt * 16 + rq;
#pragma unroll
            for (int nt = 0; nt < 8; ++nt) {
                const int col = nw + nt * 8 + c2;
                const float bx = bias ? __ldg(bias + col) : 0.f;
                const float by = bias ? __ldg(bias + col + 1) : 0.f;
                if (r0 < M)
                    *reinterpret_cast<float2*>(C + (size_t)r0 * 128 + col) =
                        make_float2(acc[mt][nt][0] + bx, acc[mt][nt][1] + by);
                if (r0 + 8 < M)
                    *reinterpret_cast<float2*>(C + (size_t)(r0 + 8) * 128 + col) =
                        make_float2(acc[mt][nt][2] + bx, acc[mt][nt][3] + by);
            }
        }
    } else {
#pragma unroll
        for (int mt = 0; mt < 2; ++mt) {
            const int rA = row0 + mw + mt * 16 + rq;
            const int rB = rA + 8;
            float invA = 0.f, invB = 0.f;
            if (rA < M) invA = 1.0f / fmaxf(__ldg(denom + rA), 1e-30f);
            if (rB < M) invB = 1.0f / fmaxf(__ldg(denom + rB), 1e-30f);
#pragma unroll
            for (int nt = 0; nt < 8; ++nt) {
                const int col = nw + nt * 8 + c2;
                if (rA < M) {
                    float2 ws = __ldg(reinterpret_cast<const float2*>(wsumh + (size_t)rA * 128 + col));
                    float2 sm = __ldg(reinterpret_cast<const float2*>(selfm + (size_t)rA * 128 + col));
                    *reinterpret_cast<float2*>(C + (size_t)rA * 128 + col) = make_float2(
                        lrelu(sm.x + (ws.x + acc[mt][nt][0]) * invA),
                        lrelu(sm.y + (ws.y + acc[mt][nt][1]) * invA));
                }
                if (rB < M) {
                    float2 ws = __ldg(reinterpret_cast<const float2*>(wsumh + (size_t)rB * 128 + col));
                    float2 sm = __ldg(reinterpret_cast<const float2*>(selfm + (size_t)rB * 128 + col));
                    *reinterpret_cast<float2*>(C + (size_t)rB * 128 + col) = make_float2(
                        lrelu(sm.x + (ws.x + acc[mt][nt][2]) * invB),
                        lrelu(sm.y + (ws.y + acc[mt][nt][3]) * invB));
                }
            }
        }
    }
}

// batched GEMM: gridDim.y selects (W, bias, C, wkn); all slices share A.
__global__ __launch_bounds__(256, 2)
void tc_gemm3(const float* __restrict__ A,
              const float* __restrict__ W0, const float* __restrict__ W1,
              const float* __restrict__ W2,
              const float* __restrict__ b0, const float* __restrict__ b1,
              const float* __restrict__ b2,
              float* __restrict__ C0, float* __restrict__ C1, float* __restrict__ C2,
              int wknMask, int M)
{
    extern __shared__ char smem[];
    const int y = blockIdx.y;
    const float* W = (y == 0) ? W0 : (y == 1) ? W1 : W2;
    const float* b = (y == 0) ? b0 : (y == 1) ? b1 : b2;
    float*       C = (y == 0) ? C0 : (y == 1) ? C1 : C2;
    gemm_body<false>(A, W, b, C, (wknMask >> y) & 1, M,
                     nullptr, nullptr, nullptr, smem);
}

// single GEMM with fused finalize epilogue
__global__ __launch_bounds__(256, 2)
void tc_gemm_fin(const float* __restrict__ A, const float* __restrict__ W,
                 float* __restrict__ out,
                 const float* __restrict__ wsumh, const float* __restrict__ denom,
                 const float* __restrict__ selfm, int M)
{
    extern __shared__ char smem[];
    gemm_body<true>(A, W, nullptr, out, 1, M, wsumh, denom, selfm, smem);
}

// ---------------------------------------------------------------------------
// CSR build (once; graph shared by both layers)
// ---------------------------------------------------------------------------
__global__ void zero_int_kernel(int* p, int n)
{
    int i = blockIdx.x * blockDim.x + threadIdx.x;
    if (i < n) p[i] = 0;
}

__global__ void deg_kernel(const int* __restrict__ dst, int* __restrict__ deg)
{
    int e = blockIdx.x * blockDim.x + threadIdx.x;
    if (e < NE) atomicAdd(deg + dst[e], 1);
}

__global__ __launch_bounds__(1024) void scan_kernel(const int* __restrict__ deg,
                                                    int* __restrict__ rowptr,
                                                    int* __restrict__ wpos)
{
    __shared__ int warpsum[32];
    __shared__ int carry_s;
    const int tid = threadIdx.x, lane = tid & 31, wid = tid >> 5;
    if (tid == 0) { carry_s = 0; rowptr[0] = 0; }
    __syncthreads();
    for (int base = 0; base < NN; base += 1024) {
        int i = base + tid;
        int v = (i < NN) ? deg[i] : 0;
        int x = v;
#pragma unroll
        for (int o = 1; o < 32; o <<= 1) {
            int y = __shfl_up_sync(0xffffffffu, x, o);
            if (lane >= o) x += y;
        }
        if (lane == 31) warpsum[wid] = x;
        __syncthreads();
        if (wid == 0) {
            int s = warpsum[lane];
#pragma unroll
            for (int o = 1; o < 32; o <<= 1) {
                int y = __shfl_up_sync(0xffffffffu, s, o);
                if (lane >= o) s += y;
            }
            warpsum[lane] = s;
        }
        __syncthreads();
        int incl = x + (wid > 0 ? warpsum[wid - 1] : 0) + carry_s;
        if (i < NN) { rowptr[i + 1] = incl; wpos[i] = incl - v; }
        __syncthreads();
        if (tid == 1023) carry_s = incl;
        __syncthreads();
    }
}

__global__ void csr_scatter(const int* __restrict__ src, const int* __restrict__ dst,
                            int* __restrict__ wpos,
                            int* __restrict__ csr_src, int* __restrict__ csr_e)
{
    int e = blockIdx.x * blockDim.x + threadIdx.x;
    if (e >= NE) return;
    int d = __ldg(dst + e);
    int p = atomicAdd(wpos + d, 1);
    csr_src[p] = __ldg(src + e);
    csr_e[p]   = e;
}

// ---------------------------------------------------------------------------
// aggregation: one warp per dst node, register accumulators,
// TWO interleaved per-edge chains (halves exposed shfl-chain depth).
// ---------------------------------------------------------------------------
__global__ __launch_bounds__(256) void agg_kernel(
    const float* __restrict__ h, const float* __restrict__ hW1,
    const float* __restrict__ g, const float* __restrict__ ef,
    const int* __restrict__ rowptr, const int* __restrict__ csr_src,
    const int* __restrict__ csr_e,
    float* __restrict__ denom, float* __restrict__ wsumh, float* __restrict__ sbuf)
{
    const int n = blockIdx.x * 8 + (threadIdx.x >> 5);
    if (n >= NN) return;
    const int lane = threadIdx.x & 31;
    const int beg = __ldg(rowptr + n), end = __ldg(rowptr + n + 1);

    float4 ah = make_float4(0.f, 0.f, 0.f, 0.f);
    float4 ae = make_float4(0.f, 0.f, 0.f, 0.f);
    float den = 0.f;

    if (beg < end) {
        const float4 hd = __ldg(reinterpret_cast<const float4*>(h) + n * 32 + lane);
        const float4 gd = __ldg(reinterpret_cast<const float4*>(g) + n * 32 + lane);

        int i = beg;
        for (; i + 1 < end; i += 2) {
            const int s0 = __ldg(csr_src + i),     e0 = __ldg(csr_e + i);
            const int s1 = __ldg(csr_src + i + 1), e1 = __ldg(csr_e + i + 1);
            const float4 hw0 = __ldg(reinterpret_cast<const float4*>(hW1) + (size_t)s0 * 32 + lane);
            const float4 ev0 = __ldg(reinterpret_cast<const float4*>(ef)  + (size_t)e0 * 32 + lane);
            const float4 hw1 = __ldg(reinterpret_cast<const float4*>(hW1) + (size_t)s1 * 32 + lane);
            const float4 ev1 = __ldg(reinterpret_cast<const float4*>(ef)  + (size_t)e1 * 32 + lane);

            float p0 = hd.x * hw0.x + hd.y * hw0.y + hd.z * hw0.z + hd.w * hw0.w
                     + gd.x * ev0.x + gd.y * ev0.y + gd.z * ev0.z + gd.w * ev0.w;
            float p1 = hd.x * hw1.x + hd.y * hw1.y + hd.z * hw1.z + hd.w * hw1.w
                     + gd.x * ev1.x + gd.y * ev1.y + gd.z * ev1.z + gd.w * ev1.w;
#pragma unroll
            for (int o = 16; o > 0; o >>= 1) {
                p0 += __shfl_xor_sync(0xffffffffu, p0, o);
                p1 += __shfl_xor_sync(0xffffffffu, p1, o);
            }
            const float w0 = __expf(p0), w1 = __expf(p1);
            ah.x += w0 * hw0.x + w1 * hw1.x;  ah.y += w0 * hw0.y + w1 * hw1.y;
            ah.z += w0 * hw0.z + w1 * hw1.z;  ah.w += w0 * hw0.w + w1 * hw1.w;
            ae.x += w0 * ev0.x + w1 * ev1.x;  ae.y += w0 * ev0.y + w1 * ev1.y;
            ae.z += w0 * ev0.z + w1 * ev1.z;  ae.w += w0 * ev0.w + w1 * ev1.w;
            den += w0 + w1;
        }
        if (i < end) {
            const int s0 = __ldg(csr_src + i), e0 = __ldg(csr_e + i);
            const float4 hw0 = __ldg(reinterpret_cast<const float4*>(hW1) + (size_t)s0 * 32 + lane);
            const float4 ev0 = __ldg(reinterpret_cast<const float4*>(ef)  + (size_t)e0 * 32 + lane);
            float p0 = hd.x * hw0.x + hd.y * hw0.y + hd.z * hw0.z + hd.w * hw0.w
                     + gd.x * ev0.x + gd.y * ev0.y + gd.z * ev0.z + gd.w * ev0.w;
#pragma unroll
            for (int o = 16; o > 0; o >>= 1) p0 += __shfl_xor_sync(0xffffffffu, p0, o);
            const float w0 = __expf(p0);
            ah.x += w0 * hw0.x; ah.y += w0 * hw0.y; ah.z += w0 * hw0.z; ah.w += w0 * hw0.w;
            ae.x += w0 * ev0.x; ae.y += w0 * ev0.y; ae.z += w0 * ev0.z; ae.w += w0 * ev0.w;
            den += w0;
        }
    }

    reinterpret_cast<float4*>(wsumh)[n * 32 + lane] = ah;
    reinterpret_cast<float4*>(sbuf)[n * 32 + lane]  = ae;
    if (lane == 0) denom[n] = den;
}

// ---------------------------------------------------------------------------
// fixup: for the rare deg==0 nodes, out = lrelu(h@W3 + b3).  warp/node.
// ---------------------------------------------------------------------------
__global__ __launch_bounds__(256) void fixup_iso(
    const float* __restrict__ h, const float* __restrict__ W3,
    const float* __restrict__ b3, const int* __restrict__ rowptr,
    float* __restrict__ out)
{
    int n = blockIdx.x * 8 + (threadIdx.x >> 5);
    if (n >= NN) return;
    if (__ldg(rowptr + n + 1) != __ldg(rowptr + n)) return;
    int lane = threadIdx.x & 31;
    int c0 = lane * 4;

    float acc0 = __ldg(b3 + c0), acc1 = __ldg(b3 + c0 + 1);
    float acc2 = __ldg(b3 + c0 + 2), acc3 = __ldg(b3 + c0 + 3);
    for (int k = 0; k < 128; ++k) {
        float hv = __ldg(h + (size_t)n * 128 + k);
        const float* wr = W3 + (size_t)k * 128 + c0;
        acc0 += hv * __ldg(wr);
        acc1 += hv * __ldg(wr + 1);
        acc2 += hv * __ldg(wr + 2);
        acc3 += hv * __ldg(wr + 3);
    }
    float4 r = make_float4(lrelu(acc0), lrelu(acc1), lrelu(acc2), lrelu(acc3));
    *reinterpret_cast<float4*>(out + (size_t)n * 128 + c0) = r;
}

// ---------------------------------------------------------------------------
// launch
// ---------------------------------------------------------------------------
extern "C" void kernel_launch(void* const* d_in, const int* in_sizes, int n_in,
                              void* d_out, int out_size)
{
    const float* node = (const float*)d_in[0];
    const float* ef   = (const float*)d_in[1];
    const int*   src  = (const int*)d_in[2];
    const int*   dst  = (const int*)d_in[3];
    const float* W1[2] = {(const float*)d_in[4],  (const float*)d_in[10]};
    const float* B1[2] = {(const float*)d_in[5],  (const float*)d_in[11]};
    const float* W2[2] = {(const float*)d_in[6],  (const float*)d_in[12]};
    const float* B2[2] = {(const float*)d_in[7],  (const float*)d_in[13]};
    const float* W3[2] = {(const float*)d_in[8],  (const float*)d_in[14]};
    const float* B3[2] = {(const float*)d_in[9],  (const float*)d_in[15]};

    float* base = nullptr;
    cudaGetSymbolAddress((void**)&base, g_scratch);

    float* hW1    = base + O_HW1;
    float* g      = base + O_G;
    float* selfm  = base + O_SELF;
    float* wsumh  = base + O_WSUM;
    float* sbuf   = base + O_S;
    float* h1     = base + O_H1;
    float* denom  = base + O_DEN;
    int*   deg    = (int*)(base + O_DEG);
    int*   rowptr = (int*)(base + O_ROWPTR);
    int*   wpos   = (int*)(base + O_WPOS);
    int*   csrs   = (int*)(base + O_CSRS);
    int*   csre   = (int*)(base + O_CSRE);

    cudaFuncSetAttribute(tc_gemm3,    cudaFuncAttributeMaxDynamicSharedMemorySize, GEMM_SMEM);
    cudaFuncSetAttribute(tc_gemm_fin, cudaFuncAttributeMaxDynamicSharedMemorySize, GEMM_SMEM);

    // ---- CSR build (once) ----
    zero_int_kernel<<<(NN + 255) / 256, 256>>>(deg, NN);
    deg_kernel<<<(NE + 255) / 256, 256>>>(dst, deg);
    scan_kernel<<<1, 1024>>>(deg, rowptr, wpos);
    csr_scatter<<<(NE + 255) / 256, 256>>>(src, dst, wpos, csrs, csre);

    const int gemmGrid = (NN + 127) / 128;   // 391
    const int nodeGrid = (NN + 7) / 8;       // 6250

    const float* h = node;
    float* out_l[2] = {h1, (float*)d_out};

    for (int l = 0; l < 2; ++l) {
        // y=0: hW1 = h@W1+b1 (wkn1);  y=1: g = h@W1^T (wkn0);  y=2: selfm (wkn1)
        tc_gemm3<<<dim3(gemmGrid, 3), 256, GEMM_SMEM>>>(
            h, W1[l], W1[l], W2[l], B1[l], nullptr, B2[l],
            hW1, g, selfm, 0b101, NN);

        agg_kernel<<<nodeGrid, 256>>>(h, hW1, g, ef, rowptr, csrs, csre,
                                      denom, wsumh, sbuf);

        // out = lrelu(selfm + (wsumh + sbuf@W1)/denom)
        tc_gemm_fin<<<gemmGrid, 256, GEMM_SMEM>>>(sbuf, W1[l], out_l[l],
                                                  wsumh, denom, selfm, NN);

        fixup_iso<<<nodeGrid, 256>>>(h, W3[l], B3[l], rowptr, out_l[l]);

        h = h1;
    }
}

// round 14
// speedup vs baseline: 1.8321x; 1.0276x over previous
#include <cuda_runtime.h>
#include <cuda_bf16.h>
#include <cstdint>

// ---------------------------------------------------------------------------
// RelGAT restructured:
//   score_e = <h[dst], hW1[src]> + <g[dst], efeat_e>,  g = h@W1^T, hW1 = h@W1+b1
//   neigh_d = ( sum w_e hW1[src] + (sum w_e efeat_e)@W1 ) / denom
// Round 13 = Round 12 resubmitted (R12 hit an infra failure, never ran).
// Design: GEMM operands pre-split to bf16 hi/lo in GMEM; GEMM fill is pure
// cp.async (all offsets 16B-aligned); K-chunked 2-CTA/SM GEMM; batched
// gridDim.y=3; fused finalize; dst-CSR agg (2-way interleave); softmax
// rescale; iso fixup.
// ---------------------------------------------------------------------------

namespace {
constexpr int    NN  = 50000;
constexpr int    NE  = 600000;
constexpr size_t ND  = (size_t)NN * 128;
constexpr float  NEG_SLOPE = 0.22916666666666666f;

constexpr size_t AL16(size_t x) { return (x + 3) & ~(size_t)3; }  // 4 floats = 16B

// scratch layout in float units — every sub-buffer 16B aligned
constexpr size_t O_HW1  = 0;
constexpr size_t O_G    = 1 * ND;
constexpr size_t O_SELF = 2 * ND;
constexpr size_t O_WSUM = 3 * ND;
constexpr size_t O_H1   = 4 * ND;
constexpr size_t O_HHI  = 5 * ND;            // ND bf16 = ND/2 floats
constexpr size_t O_HLO  = 5 * ND + ND / 2;
constexpr size_t O_SBHI = 6 * ND;
constexpr size_t O_SBLO = 6 * ND + ND / 2;
constexpr size_t O_DEN    = 7 * ND;                      // NN floats
constexpr size_t O_DEG    = AL16(O_DEN + NN);            // NN ints
constexpr size_t O_ROWPTR = AL16(O_DEG + NN);            // NN+1 ints
constexpr size_t O_WPOS   = AL16(O_ROWPTR + NN + 1);     // NN ints
constexpr size_t O_CSRS   = AL16(O_WPOS + NN);           // NE ints
constexpr size_t O_CSRE   = AL16(O_CSRS + NE);           // NE ints
constexpr size_t O_WSP    = AL16(O_CSRE + NE);           // 4 x 16384 bf16
constexpr size_t SCRATCH  = O_WSP + 32768 + 64;

// K-chunked GEMM smem (bytes), chunk K=64:
constexpr int LDA  = 144;
constexpr int LDBT = 272;
constexpr int LDBN = 144;
constexpr int A_HI = 0;
constexpr int A_LO = A_HI + 128 * LDA;       // 18432
constexpr int B_HI = A_LO + 128 * LDA;       // 36864
constexpr int B_LO = B_HI + 128 * LDBN;      // 55296
constexpr int GEMM_SMEM = B_LO + 128 * LDBN; // 73728 -> 2 CTAs/SM
}  // namespace

__device__ __align__(256) float g_scratch[SCRATCH];

// ---------------------------------------------------------------------------
// helpers
// ---------------------------------------------------------------------------
__device__ __forceinline__ uint32_t smem_u32(const void* p) {
    uint32_t a;
    asm("{ .reg .u64 t; cvta.to.shared.u64 t, %1; cvt.u32.u64 %0, t; }" : "=r"(a) : "l"(p));
    return a;
}
__device__ __forceinline__ void cpasync16(uint32_t saddr, const void* g, uint32_t srcsz) {
    asm volatile("cp.async.cg.shared.global [%0], [%1], 16, %2;"
                 :: "r"(saddr), "l"(g), "r"(srcsz) : "memory");
}
__device__ __forceinline__ void ldsm_x4(uint32_t* r, uint32_t addr) {
    asm volatile("ldmatrix.sync.aligned.m8n8.x4.shared.b16 {%0,%1,%2,%3}, [%4];"
                 : "=r"(r[0]), "=r"(r[1]), "=r"(r[2]), "=r"(r[3]) : "r"(addr));
}
__device__ __forceinline__ void ldsm_x4t(uint32_t* r, uint32_t addr) {
    asm volatile("ldmatrix.sync.aligned.m8n8.x4.trans.shared.b16 {%0,%1,%2,%3}, [%4];"
                 : "=r"(r[0]), "=r"(r[1]), "=r"(r[2]), "=r"(r[3]) : "r"(addr));
}
__device__ __forceinline__ void mma_bf16(float* d, const uint32_t* a, const uint32_t* b) {
    asm volatile("mma.sync.aligned.m16n8k16.row.col.f32.bf16.bf16.f32 "
                 "{%0,%1,%2,%3}, {%4,%5,%6,%7}, {%8,%9}, {%0,%1,%2,%3};"
                 : "+f"(d[0]), "+f"(d[1]), "+f"(d[2]), "+f"(d[3])
                 : "r"(a[0]), "r"(a[1]), "r"(a[2]), "r"(a[3]), "r"(b[0]), "r"(b[1]));
}
__device__ __forceinline__ float lrelu(float v) { return v >= 0.f ? v : v * NEG_SLOPE; }

// split float2 -> bf16 hi pair + lo(residual) pair
__device__ __forceinline__ void split2(float x, float y,
                                       __nv_bfloat162& hi, __nv_bfloat162& lo) {
    hi = __float22bfloat162_rn(make_float2(x, y));
    float2 f = __bfloat1622float2(hi);
    lo = __float22bfloat162_rn(make_float2(x - f.x, y - f.y));
}

// ---------------------------------------------------------------------------
// K-chunked GEMM body, cp.async fill from pre-split bf16 operands.
// wkn=1: W stored [k][n] (C=A@W).  wkn=0: W stored [n][k] (C=A@W^T).
// FIN: epilogue out = lrelu(selfm + (wsumh + acc)/max(denom,1e-30)); if
// outhi != nullptr also emits hi/lo bf16 of the result (next layer's A).
// ---------------------------------------------------------------------------
template <bool FIN>
__device__ __forceinline__ void gemm_body(
    const __nv_bfloat16* __restrict__ Ahi, const __nv_bfloat16* __restrict__ Alo,
    const __nv_bfloat16* __restrict__ Bhi, const __nv_bfloat16* __restrict__ Blo,
    const float* __restrict__ bias, float* __restrict__ C, int wkn, int M,
    const float* __restrict__ wsumh, const float* __restrict__ denom,
    const float* __restrict__ selfm,
    __nv_bfloat16* __restrict__ outhi, __nv_bfloat16* __restrict__ outlo,
    char* smem)
{
    const uint32_t sb = smem_u32(smem);
    const int tid = threadIdx.x, wid = tid >> 5, lane = tid & 31;
    const int row0 = blockIdx.x * 128;
    const int mw = (wid & 3) * 32, nw = (wid >> 2) * 64;

    const uint32_t a_off  = (uint32_t)((mw + (lane & 15)) * LDA + ((lane >> 4) << 4));
    const uint32_t bt_off = (uint32_t)((((lane >> 3) & 1) * 8 + (lane & 7)) * LDBT
                                       + (nw + ((lane >> 4) << 3)) * 2);
    const uint32_t bn_off = (uint32_t)((nw + ((lane >> 4) << 3) + (lane & 7)) * LDBN
                                       + ((lane >> 3) & 1) * 16);

    float acc[2][8][4];
#pragma unroll
    for (int mt = 0; mt < 2; ++mt)
#pragma unroll
        for (int nt = 0; nt < 8; ++nt)
#pragma unroll
            for (int j = 0; j < 4; ++j) acc[mt][nt][j] = 0.f;

#pragma unroll
    for (int c = 0; c < 2; ++c) {
        __syncthreads();   // protect smem reuse from previous chunk's mma

        // --- A chunk (rows 0..127, cols [c*64,c*64+64)): 128B/row hi + lo ---
        {
            const int r  = tid >> 1;
            const int j0 = (tid & 1) * 4;          // 16B-chunk index {0,4}
            const bool valid = (row0 + r) < M;
            const uint32_t ssz = valid ? 16u : 0u;
            const size_t grow = valid ? (size_t)(row0 + r) : 0;
            const char* gH = (const char*)Ahi + grow * 256 + c * 128 + j0 * 16;
            const char* gL = (const char*)Alo + grow * 256 + c * 128 + j0 * 16;
            const uint32_t sH = sb + A_HI + r * LDA + j0 * 16;
            const uint32_t sL = sb + A_LO + r * LDA + j0 * 16;
#pragma unroll
            for (int i = 0; i < 4; ++i) {
                cpasync16(sH + i * 16, gH + i * 16, ssz);
                cpasync16(sL + i * 16, gL + i * 16, ssz);
            }
        }
        // --- B chunk ---
        if (wkn) {   // [k][n]: 64 k-rows of this chunk, 256B per row
            const int kr = tid >> 2;
            const int j0 = (tid & 3) * 4;          // {0,4,8,12}
            const char* gH = (const char*)Bhi + (size_t)(c * 64 + kr) * 256 + j0 * 16;
            const char* gL = (const char*)Blo + (size_t)(c * 64 + kr) * 256 + j0 * 16;
            const uint32_t sH = sb + B_HI + kr * LDBT + j0 * 16;
            const uint32_t sL = sb + B_LO + kr * LDBT + j0 * 16;
#pragma unroll
            for (int i = 0; i < 4; ++i) {
                cpasync16(sH + i * 16, gH + i * 16, 16u);
                cpasync16(sL + i * 16, gL + i * 16, 16u);
            }
        } else {     // [n][k]: 128 n-rows, cols chunk (128B per row)
            const int nr = tid >> 1;
            const int j0 = (tid & 1) * 4;
            const char* gH = (const char*)Bhi + (size_t)nr * 256 + c * 128 + j0 * 16;
            const char* gL = (const char*)Blo + (size_t)nr * 256 + c * 128 + j0 * 16;
            const uint32_t sH = sb + B_HI + nr * LDBN + j0 * 16;
            const uint32_t sL = sb + B_LO + nr * LDBN + j0 * 16;
#pragma unroll
            for (int i = 0; i < 4; ++i) {
                cpasync16(sH + i * 16, gH + i * 16, 16u);
                cpasync16(sL + i * 16, gL + i * 16, 16u);
            }
        }
        asm volatile("cp.async.commit_group;" ::: "memory");
        asm volatile("cp.async.wait_group 0;" ::: "memory");
        __syncthreads();

        // --- MMA: 3 groups (hh, hl, lh) x 4 k16-steps ---
#pragma unroll
        for (int g = 0; g < 3; ++g) {
            const uint32_t abase = sb + (g == 2 ? A_LO : A_HI);
            const uint32_t bbase = sb + (g == 1 ? B_LO : B_HI);
#pragma unroll
            for (int kk = 0; kk < 4; ++kk) {
                uint32_t a0[4], a1[4];
                ldsm_x4(a0, abase + a_off + kk * 32);
                ldsm_x4(a1, abase + a_off + 16 * LDA + kk * 32);
#pragma unroll
                for (int p = 0; p < 4; ++p) {
                    uint32_t b4[4];
                    if (wkn)
                        ldsm_x4t(b4, bbase + bt_off + (uint32_t)(kk * 16 * LDBT + p * 32));
                    else
                        ldsm_x4(b4, bbase + bn_off + (uint32_t)(p * 16 * LDBN + kk * 32));
                    mma_bf16(acc[0][2 * p],     a0, b4);
                    mma_bf16(acc[0][2 * p + 1], a0, b4 + 2);
                    mma_bf16(acc[1][2 * p],     a1, b4);
                    mma_bf16(acc[1][2 * p + 1], a1, b4 + 2);
                }
            }
        }
    }

    // --- epilogue ---
    const int rq = lane >> 2, c2 = (lane & 3) * 2;
    if (!FIN) {
#pragma unroll
        for (int mt = 0; mt < 2; ++mt) {
            const int r0 = row0 + mw + mt * 16 + rq;
#pragma unroll
            for (int nt = 0; nt < 8; ++nt) {
                const int col = nw + nt * 8 + c2;
                const float bx = bias ? __ldg(bias + col) : 0.f;
                const float by = bias ? __ldg(bias + col + 1) : 0.f;
                if (r0 < M)
                    *reinterpret_cast<float2*>(C + (size_t)r0 * 128 + col) =
                        make_float2(acc[mt][nt][0] + bx, acc[mt][nt][1] + by);
                if (r0 + 8 < M)
                    *reinterpret_cast<float2*>(C + (size_t)(r0 + 8) * 128 + col) =
                        make_float2(acc[mt][nt][2] + bx, acc[mt][nt][3] + by);
            }
        }
    } else {
#pragma unroll
        for (int mt = 0; mt < 2; ++mt) {
            const int rA = row0 + mw + mt * 16 + rq;
            const int rB = rA + 8;
            float invA = 0.f, invB = 0.f;
            if (rA < M) invA = 1.0f / fmaxf(__ldg(denom + rA), 1e-30f);
            if (rB < M) invB = 1.0f / fmaxf(__ldg(denom + rB), 1e-30f);
#pragma unroll
            for (int nt = 0; nt < 8; ++nt) {
                const int col = nw + nt * 8 + c2;
                if (rA < M) {
                    float2 ws = __ldg(reinterpret_cast<const float2*>(wsumh + (size_t)rA * 128 + col));
                    float2 sm = __ldg(reinterpret_cast<const float2*>(selfm + (size_t)rA * 128 + col));
                    float vx = lrelu(sm.x + (ws.x + acc[mt][nt][0]) * invA);
                    float vy = lrelu(sm.y + (ws.y + acc[mt][nt][1]) * invA);
                    *reinterpret_cast<float2*>(C + (size_t)rA * 128 + col) = make_float2(vx, vy);
                    if (outhi) {
                        __nv_bfloat162 hi, lo;
                        split2(vx, vy, hi, lo);
                        *reinterpret_cast<__nv_bfloat162*>(outhi + (size_t)rA * 128 + col) = hi;
                        *reinterpret_cast<__nv_bfloat162*>(outlo + (size_t)rA * 128 + col) = lo;
                    }
                }
                if (rB < M) {
                    float2 ws = __ldg(reinterpret_cast<const float2*>(wsumh + (size_t)rB * 128 + col));
                    float2 sm = __ldg(reinterpret_cast<const float2*>(selfm + (size_t)rB * 128 + col));
                    float vx = lrelu(sm.x + (ws.x + acc[mt][nt][2]) * invB);
                    float vy = lrelu(sm.y + (ws.y + acc[mt][nt][3]) * invB);
                    *reinterpret_cast<float2*>(C + (size_t)rB * 128 + col) = make_float2(vx, vy);
                    if (outhi) {
                        __nv_bfloat162 hi, lo;
                        split2(vx, vy, hi, lo);
                        *reinterpret_cast<__nv_bfloat162*>(outhi + (size_t)rB * 128 + col) = hi;
                        *reinterpret_cast<__nv_bfloat162*>(outlo + (size_t)rB * 128 + col) = lo;
                    }
                }
            }
        }
    }
}

// batched GEMM: gridDim.y selects (B, bias, C, wkn); all slices share A.
__global__ __launch_bounds__(256, 2)
void tc_gemm3(const __nv_bfloat16* __restrict__ Ahi, const __nv_bfloat16* __restrict__ Alo,
              const __nv_bfloat16* __restrict__ w1h, const __nv_bfloat16* __restrict__ w1l,
              const __nv_bfloat16* __restrict__ w2h, const __nv_bfloat16* __restrict__ w2l,
              const float* __restrict__ b0, const float* __restrict__ b2,
              float* __restrict__ C0, float* __restrict__ C1, float* __restrict__ C2,
              int M)
{
    extern __shared__ char smem[];
    const int y = blockIdx.y;
    const __nv_bfloat16* Bh = (y == 2) ? w2h : w1h;
    const __nv_bfloat16* Bl = (y == 2) ? w2l : w1l;
    const float* b = (y == 0) ? b0 : (y == 1) ? nullptr : b2;
    float*       C = (y == 0) ? C0 : (y == 1) ? C1 : C2;
    const int wkn = (y == 1) ? 0 : 1;
    gemm_body<false>(Ahi, Alo, Bh, Bl, b, C, wkn, M,
                     nullptr, nullptr, nullptr, nullptr, nullptr, smem);
}

// single GEMM with fused finalize epilogue
__global__ __launch_bounds__(256, 2)
void tc_gemm_fin(const __nv_bfloat16* __restrict__ Ahi, const __nv_bfloat16* __restrict__ Alo,
                 const __nv_bfloat16* __restrict__ Bhi, const __nv_bfloat16* __restrict__ Blo,
                 float* __restrict__ out,
                 const float* __restrict__ wsumh, const float* __restrict__ denom,
                 const float* __restrict__ selfm,
                 __nv_bfloat16* __restrict__ outhi, __nv_bfloat16* __restrict__ outlo, int M)
{
    extern __shared__ char smem[];
    gemm_body<true>(Ahi, Alo, Bhi, Blo, nullptr, out, 1, M,
                    wsumh, denom, selfm, outhi, outlo, smem);
}

// ---------------------------------------------------------------------------
// split kernels
// ---------------------------------------------------------------------------
__global__ void hsplit_kernel(const float* __restrict__ x,
                              __nv_bfloat16* __restrict__ hi, __nv_bfloat16* __restrict__ lo)
{
    size_t i = ((size_t)blockIdx.x * blockDim.x + threadIdx.x) * 2;
    if (i >= ND) return;
    float2 v = *reinterpret_cast<const float2*>(x + i);
    __nv_bfloat162 h2, l2;
    split2(v.x, v.y, h2, l2);
    *reinterpret_cast<__nv_bfloat162*>(hi + i) = h2;
    *reinterpret_cast<__nv_bfloat162*>(lo + i) = l2;
}

__global__ void wsplit_kernel(const float* __restrict__ W1, const float* __restrict__ W2,
                              __nv_bfloat16* __restrict__ w1h, __nv_bfloat16* __restrict__ w1l,
                              __nv_bfloat16* __restrict__ w2h, __nv_bfloat16* __restrict__ w2l)
{
    int i = (blockIdx.x * blockDim.x + threadIdx.x) * 2;
    if (i >= 16384) return;
    float2 v = *reinterpret_cast<const float2*>(W1 + i);
    __nv_bfloat162 h2, l2;
    split2(v.x, v.y, h2, l2);
    *reinterpret_cast<__nv_bfloat162*>(w1h + i) = h2;
    *reinterpret_cast<__nv_bfloat162*>(w1l + i) = l2;
    v = *reinterpret_cast<const float2*>(W2 + i);
    split2(v.x, v.y, h2, l2);
    *reinterpret_cast<__nv_bfloat162*>(w2h + i) = h2;
    *reinterpret_cast<__nv_bfloat162*>(w2l + i) = l2;
}

// ---------------------------------------------------------------------------
// CSR build (once; graph shared by both layers)
// ---------------------------------------------------------------------------
__global__ void zero_int_kernel(int* p, int n)
{
    int i = blockIdx.x * blockDim.x + threadIdx.x;
    if (i < n) p[i] = 0;
}

__global__ void deg_kernel(const int* __restrict__ dst, int* __restrict__ deg)
{
    int e = blockIdx.x * blockDim.x + threadIdx.x;
    if (e < NE) atomicAdd(deg + dst[e], 1);
}

__global__ __launch_bounds__(1024) void scan_kernel(const int* __restrict__ deg,
                                                    int* __restrict__ rowptr,
                                                    int* __restrict__ wpos)
{
    __shared__ int warpsum[32];
    __shared__ int carry_s;
    const int tid = threadIdx.x, lane = tid & 31, wid = tid >> 5;
    if (tid == 0) { carry_s = 0; rowptr[0] = 0; }
    __syncthreads();
    for (int base = 0; base < NN; base += 1024) {
        int i = base + tid;
        int v = (i < NN) ? deg[i] : 0;
        int x = v;
#pragma unroll
        for (int o = 1; o < 32; o <<= 1) {
            int y = __shfl_up_sync(0xffffffffu, x, o);
            if (lane >= o) x += y;
        }
        if (lane == 31) warpsum[wid] = x;
        __syncthreads();
        if (wid == 0) {
            int s = warpsum[lane];
#pragma unroll
            for (int o = 1; o < 32; o <<= 1) {
                int y = __shfl_up_sync(0xffffffffu, s, o);
                if (lane >= o) s += y;
            }
            warpsum[lane] = s;
        }
        __syncthreads();
        int incl = x + (wid > 0 ? warpsum[wid - 1] : 0) + carry_s;
        if (i < NN) { rowptr[i + 1] = incl; wpos[i] = incl - v; }
        __syncthreads();
        if (tid == 1023) carry_s = incl;
        __syncthreads();
    }
}

__global__ void csr_scatter(const int* __restrict__ src, const int* __restrict__ dst,
                            int* __restrict__ wpos,
                            int* __restrict__ csr_src, int* __restrict__ csr_e)
{
    int e = blockIdx.x * blockDim.x + threadIdx.x;
    if (e >= NE) return;
    int d = __ldg(dst + e);
    int p = atomicAdd(wpos + d, 1);
    csr_src[p] = __ldg(src + e);
    csr_e[p]   = e;
}

// ---------------------------------------------------------------------------
// aggregation: one warp per dst node, 2-way interleaved chains;
// sbuf emitted directly as bf16 hi/lo (A-operand of the fin GEMM).
// ---------------------------------------------------------------------------
__global__ __launch_bounds__(256) void agg_kernel(
    const float* __restrict__ h, const float* __restrict__ hW1,
    const float* __restrict__ g, const float* __restrict__ ef,
    const int* __restrict__ rowptr, const int* __restrict__ csr_src,
    const int* __restrict__ csr_e,
    float* __restrict__ denom, float* __restrict__ wsumh,
    __nv_bfloat16* __restrict__ sbhi, __nv_bfloat16* __restrict__ sblo)
{
    const int n = blockIdx.x * 8 + (threadIdx.x >> 5);
    if (n >= NN) return;
    const int lane = threadIdx.x & 31;
    const int beg = __ldg(rowptr + n), end = __ldg(rowptr + n + 1);

    float4 ah = make_float4(0.f, 0.f, 0.f, 0.f);
    float4 ae = make_float4(0.f, 0.f, 0.f, 0.f);
    float den = 0.f;

    if (beg < end) {
        const float4 hd = __ldg(reinterpret_cast<const float4*>(h) + n * 32 + lane);
        const float4 gd = __ldg(reinterpret_cast<const float4*>(g) + n * 32 + lane);

        int i = beg;
        for (; i + 1 < end; i += 2) {
            const int s0 = __ldg(csr_src + i),     e0 = __ldg(csr_e + i);
            const int s1 = __ldg(csr_src + i + 1), e1 = __ldg(csr_e + i + 1);
            const float4 hw0 = __ldg(reinterpret_cast<const float4*>(hW1) + (size_t)s0 * 32 + lane);
            const float4 ev0 = __ldg(reinterpret_cast<const float4*>(ef)  + (size_t)e0 * 32 + lane);
            const float4 hw1 = __ldg(reinterpret_cast<const float4*>(hW1) + (size_t)s1 * 32 + lane);
            const float4 ev1 = __ldg(reinterpret_cast<const float4*>(ef)  + (size_t)e1 * 32 + lane);

            float p0 = hd.x * hw0.x + hd.y * hw0.y + hd.z * hw0.z + hd.w * hw0.w
                     + gd.x * ev0.x + gd.y * ev0.y + gd.z * ev0.z + gd.w * ev0.w;
            float p1 = hd.x * hw1.x + hd.y * hw1.y + hd.z * hw1.z + hd.w * hw1.w
                     + gd.x * ev1.x + gd.y * ev1.y + gd.z * ev1.z + gd.w * ev1.w;
#pragma unroll
            for (int o = 16; o > 0; o >>= 1) {
                p0 += __shfl_xor_sync(0xffffffffu, p0, o);
                p1 += __shfl_xor_sync(0xffffffffu, p1, o);
            }
            const float w0 = __expf(p0), w1 = __expf(p1);
            ah.x += w0 * hw0.x + w1 * hw1.x;  ah.y += w0 * hw0.y + w1 * hw1.y;
            ah.z += w0 * hw0.z + w1 * hw1.z;  ah.w += w0 * hw0.w + w1 * hw1.w;
            ae.x += w0 * ev0.x + w1 * ev1.x;  ae.y += w0 * ev0.y + w1 * ev1.y;
            ae.z += w0 * ev0.z + w1 * ev1.z;  ae.w += w0 * ev0.w + w1 * ev1.w;
            den += w0 + w1;
        }
        if (i < end) {
            const int s0 = __ldg(csr_src + i), e0 = __ldg(csr_e + i);
            const float4 hw0 = __ldg(reinterpret_cast<const float4*>(hW1) + (size_t)s0 * 32 + lane);
            const float4 ev0 = __ldg(reinterpret_cast<const float4*>(ef)  + (size_t)e0 * 32 + lane);
            float p0 = hd.x * hw0.x + hd.y * hw0.y + hd.z * hw0.z + hd.w * hw0.w
                     + gd.x * ev0.x + gd.y * ev0.y + gd.z * ev0.z + gd.w * ev0.w;
#pragma unroll
            for (int o = 16; o > 0; o >>= 1) p0 += __shfl_xor_sync(0xffffffffu, p0, o);
            const float w0 = __expf(p0);
            ah.x += w0 * hw0.x; ah.y += w0 * hw0.y; ah.z += w0 * hw0.z; ah.w += w0 * hw0.w;
            ae.x += w0 * ev0.x; ae.y += w0 * ev0.y; ae.z += w0 * ev0.z; ae.w += w0 * ev0.w;
            den += w0;
        }
    }

    reinterpret_cast<float4*>(wsumh)[n * 32 + lane] = ah;
    {
        const size_t idx = (size_t)n * 128 + lane * 4;
        __nv_bfloat162 h01, l01, h23, l23;
        split2(ae.x, ae.y, h01, l01);
        split2(ae.z, ae.w, h23, l23);
        *reinterpret_cast<__nv_bfloat162*>(sbhi + idx)     = h01;
        *reinterpret_cast<__nv_bfloat162*>(sbhi + idx + 2) = h23;
        *reinterpret_cast<__nv_bfloat162*>(sblo + idx)     = l01;
        *reinterpret_cast<__nv_bfloat162*>(sblo + idx + 2) = l23;
    }
    if (lane == 0) denom[n] = den;
}

// ---------------------------------------------------------------------------
// fixup: for the rare deg==0 nodes, out = lrelu(h@W3 + b3).  warp/node.
// Also refreshes the hi/lo split of those rows when outhi != nullptr.
// ---------------------------------------------------------------------------
__global__ __launch_bounds__(256) void fixup_iso(
    const float* __restrict__ h, const float* __restrict__ W3,
    const float* __restrict__ b3, const int* __restrict__ rowptr,
    float* __restrict__ out,
    __nv_bfloat16* __restrict__ outhi, __nv_bfloat16* __restrict__ outlo)
{
    int n = blockIdx.x * 8 + (threadIdx.x >> 5);
    if (n >= NN) return;
    if (__ldg(rowptr + n + 1) != __ldg(rowptr + n)) return;
    int lane = threadIdx.x & 31;
    int c0 = lane * 4;

    float acc0 = __ldg(b3 + c0), acc1 = __ldg(b3 + c0 + 1);
    float acc2 = __ldg(b3 + c0 + 2), acc3 = __ldg(b3 + c0 + 3);
    for (int k = 0; k < 128; ++k) {
        float hv = __ldg(h + (size_t)n * 128 + k);
        const float* wr = W3 + (size_t)k * 128 + c0;
        acc0 += hv * __ldg(wr);
        acc1 += hv * __ldg(wr + 1);
        acc2 += hv * __ldg(wr + 2);
        acc3 += hv * __ldg(wr + 3);
    }
    float4 r = make_float4(lrelu(acc0), lrelu(acc1), lrelu(acc2), lrelu(acc3));
    *reinterpret_cast<float4*>(out + (size_t)n * 128 + c0) = r;
    if (outhi) {
        __nv_bfloat162 h01, l01, h23, l23;
        split2(r.x, r.y, h01, l01);
        split2(r.z, r.w, h23, l23);
        const size_t idx = (size_t)n * 128 + c0;
        *reinterpret_cast<__nv_bfloat162*>(outhi + idx)     = h01;
        *reinterpret_cast<__nv_bfloat162*>(outhi + idx + 2) = h23;
        *reinterpret_cast<__nv_bfloat162*>(outlo + idx)     = l01;
        *reinterpret_cast<__nv_bfloat162*>(outlo + idx + 2) = l23;
    }
}

// ---------------------------------------------------------------------------
// launch
// ---------------------------------------------------------------------------
extern "C" void kernel_launch(void* const* d_in, const int* in_sizes, int n_in,
                              void* d_out, int out_size)
{
    const float* node = (const float*)d_in[0];
    const float* ef   = (const float*)d_in[1];
    const int*   src  = (const int*)d_in[2];
    const int*   dst  = (const int*)d_in[3];
    const float* W1[2] = {(const float*)d_in[4],  (const float*)d_in[10]};
    const float* B1[2] = {(const float*)d_in[5],  (const float*)d_in[11]};
    const float* W2[2] = {(const float*)d_in[6],  (const float*)d_in[12]};
    const float* B2[2] = {(const float*)d_in[7],  (const float*)d_in[13]};
    const float* W3[2] = {(const float*)d_in[8],  (const float*)d_in[14]};
    const float* B3[2] = {(const float*)d_in[9],  (const float*)d_in[15]};

    float* base = nullptr;
    cudaGetSymbolAddress((void**)&base, g_scratch);

    float* hW1    = base + O_HW1;
    float* g      = base + O_G;
    float* selfm  = base + O_SELF;
    float* wsumh  = base + O_WSUM;
    float* h1     = base + O_H1;
    __nv_bfloat16* hhi  = (__nv_bfloat16*)(base + O_HHI);
    __nv_bfloat16* hlo  = (__nv_bfloat16*)(base + O_HLO);
    __nv_bfloat16* sbhi = (__nv_bfloat16*)(base + O_SBHI);
    __nv_bfloat16* sblo = (__nv_bfloat16*)(base + O_SBLO);
    float* denom  = base + O_DEN;
    int*   deg    = (int*)(base + O_DEG);
    int*   rowptr = (int*)(base + O_ROWPTR);
    int*   wpos   = (int*)(base + O_WPOS);
    int*   csrs   = (int*)(base + O_CSRS);
    int*   csre   = (int*)(base + O_CSRE);
    __nv_bfloat16* w1h = (__nv_bfloat16*)(base + O_WSP);
    __nv_bfloat16* w1l = w1h + 16384;
    __nv_bfloat16* w2h = w1l + 16384;
    __nv_bfloat16* w2l = w2h + 16384;

    cudaFuncSetAttribute(tc_gemm3,    cudaFuncAttributeMaxDynamicSharedMemorySize, GEMM_SMEM);
    cudaFuncSetAttribute(tc_gemm_fin, cudaFuncAttributeMaxDynamicSharedMemorySize, GEMM_SMEM);

    // ---- CSR build (once) ----
    zero_int_kernel<<<(NN + 255) / 256, 256>>>(deg, NN);
    deg_kernel<<<(NE + 255) / 256, 256>>>(dst, deg);
    scan_kernel<<<1, 1024>>>(deg, rowptr, wpos);
    csr_scatter<<<(NE + 255) / 256, 256>>>(src, dst, wpos, csrs, csre);

    // ---- split layer-0 A operand (node feats) ----
    hsplit_kernel<<<(int)((ND / 2 + 255) / 256), 256>>>(node, hhi, hlo);

    const int gemmGrid = (NN + 127) / 128;   // 391
    const int nodeGrid = (NN + 7) / 8;       // 6250

    const float* h = node;
    float* out_l[2] = {h1, (float*)d_out};

    for (int l = 0; l < 2; ++l) {
        wsplit_kernel<<<32, 256>>>(W1[l], W2[l], w1h, w1l, w2h, w2l);

        // y=0: hW1 = h@W1+b1;  y=1: g = h@W1^T;  y=2: selfm = h@W2+b2
        tc_gemm3<<<dim3(gemmGrid, 3), 256, GEMM_SMEM>>>(
            hhi, hlo, w1h, w1l, w2h, w2l, B1[l], B2[l],
            hW1, g, selfm, NN);

        agg_kernel<<<nodeGrid, 256>>>(h, hW1, g, ef, rowptr, csrs, csre,
                                      denom, wsumh, sbhi, sblo);

        // out = lrelu(selfm + (wsumh + sbuf@W1)/denom); layer0 also emits
        // hi/lo split of h1 (A operand for layer1).
        tc_gemm_fin<<<gemmGrid, 256, GEMM_SMEM>>>(
            sbhi, sblo, w1h, w1l, out_l[l], wsumh, denom, selfm,
            (l == 0) ? hhi : nullptr, (l == 0) ? hlo : nullptr, NN);

        fixup_iso<<<nodeGrid, 256>>>(h, W3[l], B3[l], rowptr, out_l[l],
                                     (l == 0) ? hhi : nullptr,
                                     (l == 0) ? hlo : nullptr);

        h = h1;
    }
}